// round 4
// baseline (speedup 1.0000x reference)
#include <cuda_runtime.h>
#include <math.h>

#define PN 22
#define DN 3
#define HN 64
#define LN 5
#define NWARP 11
#define NTHREADS 352
#define CRC 3.0f       /* 15.0 / 5 layers */
#define LOG2M 7.0f

typedef unsigned long long ull;

/* ---- shared memory layout (floats) ---- */
constexpr int OFF_EW1 = 0;                     /* 130*64 = 8320 */
constexpr int OFF_EW2 = 8320;                  /* 64*64 */
constexpr int OFF_NW1 = 12416;                 /* 128*64 */
constexpr int OFF_NW2 = 20608;                 /* 64*64 */
constexpr int OFF_CW1 = 24704;                 /* 64*64 */
constexpr int OFF_CW2 = 28800;                 /* 64 */
constexpr int OFF_AW  = 28864;
constexpr int OFF_EB1 = 28928;
constexpr int OFF_EB2 = 28992;
constexpr int OFF_NB1 = 29056;
constexpr int OFF_NB2 = 29120;
constexpr int OFF_CB1 = 29184;
constexpr int OFF_H   = 29248;                 /* 22*64 */
constexpr int OFF_HR  = 30656;                 /* 22*64 */
constexpr int OFF_HC  = 32064;                 /* 22*64 */
constexpr int OFF_EA  = 33472;                 /* 22*22=484, pad to 488 */
constexpr int OFF_WB  = 33960;                 /* 11 warps * 8 edges * 64 ull = 11264 floats */
constexpr int OFF_CRD = 45224;                 /* 66 -> pad 68 */
constexpr int OFF_CR0 = 45292;
constexpr int OFF_VEL = 45360;
constexpr int OFF_MEAN = 45428;
constexpr int OFF_AB  = 45432;
constexpr int SMEM_FLOATS = 45436;             /* 181,744 bytes */

__device__ __forceinline__ float siluf(float v) { return v / (1.f + __expf(-v)); }
__device__ __forceinline__ float sigmf_(float v) { return 1.f / (1.f + __expf(-v)); }

__device__ __forceinline__ void ffma2(ull& d, ull a, ull b) {
    asm("fma.rn.f32x2 %0, %1, %2, %0;" : "+l"(d) : "l"(a), "l"(b));
}
__device__ __forceinline__ ull add2(ull a, ull b) {
    ull r; asm("add.rn.f32x2 %0, %1, %2;" : "=l"(r) : "l"(a), "l"(b)); return r;
}
__device__ __forceinline__ ull pack2(float x, float y) {
    ull r; asm("mov.b64 %0, {%1, %2};" : "=l"(r) : "f"(x), "f"(y)); return r;
}
__device__ __forceinline__ void unpack2(ull v, float& x, float& y) {
    asm("mov.b64 {%0, %1}, %2;" : "=f"(x), "=f"(y) : "l"(v));
}

/* 8-edge-batched GEMV with packed FFMA2.
   Wm: 64x64 row-major (floats). act: 8 rows of 64 ull, each ull = {a,a} duplicated.
   u[e] accumulates output cols (2*lane, 2*lane+1) as f32x2. */
__device__ __forceinline__ void gemv8(const float* __restrict__ Wm,
                                      const ull* __restrict__ act,
                                      const int lane, ull u[8])
{
#pragma unroll 8
    for (int k = 0; k < HN; k += 2) {
        const ull w0 = *(const ull*)&Wm[k * HN + 2 * lane];
        const ull w1 = *(const ull*)&Wm[(k + 1) * HN + 2 * lane];
#pragma unroll
        for (int e = 0; e < 8; ++e) {
            const ulonglong2 a = *(const ulonglong2*)&act[e * HN + k];
            ffma2(u[e], a.x, w0);
            ffma2(u[e], a.y, w1);
        }
    }
}

__global__ __launch_bounds__(NTHREADS, 1)
void egnn_kernel(const float* __restrict__ t, const float* __restrict__ x,
                 const float* __restrict__ embW, const float* __restrict__ embb,
                 const float* __restrict__ ew1, const float* __restrict__ eb1,
                 const float* __restrict__ ew2, const float* __restrict__ eb2,
                 const float* __restrict__ nw1, const float* __restrict__ nb1,
                 const float* __restrict__ nw2, const float* __restrict__ nb2,
                 const float* __restrict__ cw1, const float* __restrict__ cb1,
                 const float* __restrict__ cw2, const float* __restrict__ aw,
                 const float* __restrict__ ab, float* __restrict__ out)
{
    extern __shared__ float sm[];
    const int tid = threadIdx.x;
    const int b = blockIdx.x;
    const int w = tid >> 5;
    const int lane = tid & 31;

    /* ---- init: coords, h ---- */
    for (int idx = tid; idx < PN * DN; idx += NTHREADS) {
        const float c = x[b * (PN * DN) + idx];
        sm[OFF_CRD + idx] = c;
        sm[OFF_CR0 + idx] = c;
    }
    const float tb = t[b];
    for (int idx = tid; idx < PN * HN; idx += NTHREADS) {
        const int i = idx >> 6, o = idx & 63;
        sm[OFF_H + idx] = embW[i * HN + o] + tb * embW[22 * HN + o]
                        + LOG2M * embW[23 * HN + o] + embb[o];
    }
    __syncthreads();
    /* edge_attr = initial squared distances */
    for (int idx = tid; idx < PN * PN; idx += NTHREADS) {
        const int i = idx / PN, j = idx % PN;
        const float dx = sm[OFF_CRD + i * 3 + 0] - sm[OFF_CRD + j * 3 + 0];
        const float dy = sm[OFF_CRD + i * 3 + 1] - sm[OFF_CRD + j * 3 + 1];
        const float dz = sm[OFF_CRD + i * 3 + 2] - sm[OFF_CRD + j * 3 + 2];
        sm[OFF_EA + idx] = dx * dx + dy * dy + dz * dz;
    }
    /* barrier after weight staging below orders EA before use */

    ull* const wbu = (ull*)(sm + OFF_WB) + (size_t)w * 8 * HN;

    for (int l = 0; l < LN; ++l) {
        /* ---- stage this layer's weights into shared ---- */
        {
            const float* s1 = ew1 + l * 130 * 64;
            for (int q = tid; q < 130 * 64; q += NTHREADS) sm[OFF_EW1 + q] = s1[q];
            const float* s2 = ew2 + l * 4096;
            for (int q = tid; q < 4096; q += NTHREADS) sm[OFF_EW2 + q] = s2[q];
            const float* s3 = nw1 + l * 8192;
            for (int q = tid; q < 8192; q += NTHREADS) sm[OFF_NW1 + q] = s3[q];
            const float* s4 = nw2 + l * 4096;
            for (int q = tid; q < 4096; q += NTHREADS) sm[OFF_NW2 + q] = s4[q];
            const float* s5 = cw1 + l * 4096;
            for (int q = tid; q < 4096; q += NTHREADS) sm[OFF_CW1 + q] = s5[q];
            if (tid < 64) {
                sm[OFF_CW2 + tid] = cw2[l * 64 + tid];
                sm[OFF_AW + tid]  = aw[l * 64 + tid];
                sm[OFF_EB1 + tid] = eb1[l * 64 + tid];
                sm[OFF_EB2 + tid] = eb2[l * 64 + tid];
                sm[OFF_NB1 + tid] = nb1[l * 64 + tid];
                sm[OFF_NB2 + tid] = nb2[l * 64 + tid];
                sm[OFF_CB1 + tid] = cb1[l * 64 + tid];
            }
            if (tid == 0) sm[OFF_AB] = ab[l];
        }
        __syncthreads();

        /* ---- phase 1: Hr = h@W1[0:64], Hc = h@W1[64:128] (packed) ---- */
#pragma unroll
        for (int nn = 0; nn < 2; ++nn) {
            const int i = w * 2 + nn;
            ull r2 = 0ull, c2 = 0ull;
#pragma unroll 8
            for (int k = 0; k < HN; ++k) {
                const float a = sm[OFF_H + i * HN + k];
                const ull ap = pack2(a, a);
                ffma2(r2, ap, *(const ull*)&sm[OFF_EW1 + k * HN + 2 * lane]);
                ffma2(c2, ap, *(const ull*)&sm[OFF_EW1 + (64 + k) * HN + 2 * lane]);
            }
            *(ull*)&sm[OFF_HR + i * HN + 2 * lane] = r2;
            *(ull*)&sm[OFF_HC + i * HN + 2 * lane] = c2;
        }
        __syncthreads();

        /* ---- phase 2: edges, 8 at a time per warp ---- */
        float aggL[2][2];
        float dcd[2][3];
        for (int nn = 0; nn < 2; ++nn) {
            const int i = w * 2 + nn;
            float agg0 = 0.f, agg1 = 0.f, dc0 = 0.f, dc1 = 0.f, dc2 = 0.f;
            const float cix = sm[OFF_CRD + i * 3 + 0];
            const float ciy = sm[OFF_CRD + i * 3 + 1];
            const float ciz = sm[OFF_CRD + i * 3 + 2];
            const ull hrp   = *(const ull*)&sm[OFF_HR + i * HN + 2 * lane];
            const ull w128p = *(const ull*)&sm[OFF_EW1 + 128 * HN + 2 * lane];
            const ull w129p = *(const ull*)&sm[OFF_EW1 + 129 * HN + 2 * lane];
            const ull b1p   = *(const ull*)&sm[OFF_EB1 + 2 * lane];
            const ull b2p   = *(const ull*)&sm[OFF_EB2 + 2 * lane];
            const ull cbp   = *(const ull*)&sm[OFF_CB1 + 2 * lane];
            const float aw0  = sm[OFF_AW + 2 * lane];
            const float aw1  = sm[OFF_AW + 2 * lane + 1];
            const float cw20 = sm[OFF_CW2 + 2 * lane];
            const float cw21 = sm[OFF_CW2 + 2 * lane + 1];
            const float abv  = sm[OFF_AB];

            for (int g = 0; g < 3; ++g) {
                float ndx[8], ndy[8], ndz[8];
                /* stage t1 = silu(e_in @ ew1 + eb1), duplicated {v,v} */
#pragma unroll
                for (int e = 0; e < 8; ++e) {
                    const int jraw = g * 8 + e;
                    int j = (jraw < i) ? jraw : jraw + 1;
                    if (j >= PN) j = i;               /* dummy self-edge */
                    const float dx = cix - sm[OFF_CRD + j * 3 + 0];
                    const float dy = ciy - sm[OFF_CRD + j * 3 + 1];
                    const float dz = ciz - sm[OFF_CRD + j * 3 + 2];
                    const float radial = dx * dx + dy * dy + dz * dz;
                    const float inv = 1.f / (sqrtf(radial) + 1.f);
                    ndx[e] = dx * inv; ndy[e] = dy * inv; ndz[e] = dz * inv;
                    const float eav = sm[OFF_EA + i * PN + j];
                    ull p = add2(add2(hrp, *(const ull*)&sm[OFF_HC + j * HN + 2 * lane]), b1p);
                    ffma2(p, pack2(radial, radial), w128p);
                    ffma2(p, pack2(eav, eav), w129p);
                    float p0, p1; unpack2(p, p0, p1);
                    const float v0 = siluf(p0), v1 = siluf(p1);
                    wbu[e * HN + 2 * lane]     = pack2(v0, v0);
                    wbu[e * HN + 2 * lane + 1] = pack2(v1, v1);
                }
                __syncwarp();

                /* GEMV2: m = silu(t1 @ ew2 + eb2) */
                ull u[8];
#pragma unroll
                for (int e = 0; e < 8; ++e) u[e] = b2p;
                gemv8(&sm[OFF_EW2], wbu, lane, u);

                float m0[8], m1[8], part[8];
#pragma unroll
                for (int e = 0; e < 8; ++e) {
                    float x0, x1; unpack2(u[e], x0, x1);
                    m0[e] = siluf(x0); m1[e] = siluf(x1);
                    part[e] = m0[e] * aw0 + m1[e] * aw1;
                }
#pragma unroll
                for (int off = 16; off; off >>= 1)
#pragma unroll
                    for (int e = 0; e < 8; ++e)
                        part[e] += __shfl_xor_sync(0xffffffffu, part[e], off);
#pragma unroll
                for (int e = 0; e < 8; ++e) {
                    const float gate = sigmf_(part[e] + abv);
                    m0[e] *= gate; m1[e] *= gate;
                }
                __syncwarp();   /* gemv2 reads of t1 complete */
#pragma unroll
                for (int e = 0; e < 8; ++e) {
                    wbu[e * HN + 2 * lane]     = pack2(m0[e], m0[e]);
                    wbu[e * HN + 2 * lane + 1] = pack2(m1[e], m1[e]);
                }
                __syncwarp();

                /* GEMV3: c1 = silu(m @ cw1 + cb1); scal = tanh(c1 @ cw2)*CR */
                ull q[8];
#pragma unroll
                for (int e = 0; e < 8; ++e) q[e] = cbp;
                gemv8(&sm[OFF_CW1], wbu, lane, q);

                float s[8];
#pragma unroll
                for (int e = 0; e < 8; ++e) {
                    float x0, x1; unpack2(q[e], x0, x1);
                    s[e] = siluf(x0) * cw20 + siluf(x1) * cw21;
                }
#pragma unroll
                for (int off = 16; off; off >>= 1)
#pragma unroll
                    for (int e = 0; e < 8; ++e)
                        s[e] += __shfl_xor_sync(0xffffffffu, s[e], off);
#pragma unroll
                for (int e = 0; e < 8; ++e) {
                    const float scal = tanhf(s[e]) * CRC;
                    dc0 += ndx[e] * scal;
                    dc1 += ndy[e] * scal;
                    dc2 += ndz[e] * scal;
                    if (g * 8 + e < PN - 1) { agg0 += m0[e]; agg1 += m1[e]; }
                }
                __syncwarp();   /* reads of m done before next group rewrites wbu */
            }
            aggL[nn][0] = agg0; aggL[nn][1] = agg1;
            dcd[nn][0] = dc0; dcd[nn][1] = dc1; dcd[nn][2] = dc2;
        }
        __syncthreads();   /* all reads of coord/Hr/Hc complete */

        /* ---- phase 3: coord update + node MLP (owner warp, no atomics) ---- */
        float* const wbf = (float*)wbu;
#pragma unroll
        for (int nn = 0; nn < 2; ++nn) {
            const int i = w * 2 + nn;
            if (lane == 0) {
                sm[OFF_CRD + i * 3 + 0] += dcd[nn][0];
                sm[OFF_CRD + i * 3 + 1] += dcd[nn][1];
                sm[OFF_CRD + i * 3 + 2] += dcd[nn][2];
            }
            wbf[2 * lane] = aggL[nn][0];
            wbf[2 * lane + 1] = aggL[nn][1];
            __syncwarp();
            ull g2 = *(const ull*)&sm[OFF_NB1 + 2 * lane];
#pragma unroll 8
            for (int k = 0; k < HN; ++k) {
                const float a = sm[OFF_H + i * HN + k];
                ffma2(g2, pack2(a, a), *(const ull*)&sm[OFF_NW1 + k * HN + 2 * lane]);
            }
#pragma unroll 8
            for (int k = 0; k < HN; ++k) {
                const float a = wbf[k];
                ffma2(g2, pack2(a, a), *(const ull*)&sm[OFF_NW1 + (HN + k) * HN + 2 * lane]);
            }
            float g0, g1; unpack2(g2, g0, g1);
            g0 = siluf(g0); g1 = siluf(g1);
            __syncwarp();
            wbf[2 * lane] = g0; wbf[2 * lane + 1] = g1;
            __syncwarp();
            ull o2 = *(const ull*)&sm[OFF_NB2 + 2 * lane];
#pragma unroll 8
            for (int k = 0; k < HN; ++k) {
                const float a = wbf[k];
                ffma2(o2, pack2(a, a), *(const ull*)&sm[OFF_NW2 + k * HN + 2 * lane]);
            }
            float o0, o1; unpack2(o2, o0, o1);
            sm[OFF_H + i * HN + 2 * lane]     += o0;
            sm[OFF_H + i * HN + 2 * lane + 1] += o1;
            __syncwarp();
        }
        __syncthreads();
    } /* layer loop */

    /* ---- velocity + mean removal ---- */
    for (int idx = tid; idx < PN * DN; idx += NTHREADS)
        sm[OFF_VEL + idx] = sm[OFF_CRD + idx] - sm[OFF_CR0 + idx];
    __syncthreads();
    if (tid < DN) {
        float s = 0.f;
        for (int i = 0; i < PN; ++i) s += sm[OFF_VEL + i * 3 + tid];
        sm[OFF_MEAN + tid] = s * (1.f / PN);
    }
    __syncthreads();
    for (int idx = tid; idx < PN * DN; idx += NTHREADS)
        out[b * (PN * DN) + idx] = sm[OFF_VEL + idx] - sm[OFF_MEAN + idx % 3];
}

extern "C" void kernel_launch(void* const* d_in, const int* in_sizes, int n_in,
                              void* d_out, int out_size)
{
    const float* t    = (const float*)d_in[0];
    const float* x    = (const float*)d_in[1];
    const float* embW = (const float*)d_in[2];
    const float* embb = (const float*)d_in[3];
    /* d_in[4] out_W, d_in[5] out_b: dead code (output depends only on coords) */
    const float* ew1  = (const float*)d_in[6];
    const float* eb1  = (const float*)d_in[7];
    const float* ew2  = (const float*)d_in[8];
    const float* eb2  = (const float*)d_in[9];
    const float* nw1  = (const float*)d_in[10];
    const float* nb1  = (const float*)d_in[11];
    const float* nw2  = (const float*)d_in[12];
    const float* nb2  = (const float*)d_in[13];
    const float* cw1  = (const float*)d_in[14];
    const float* cb1  = (const float*)d_in[15];
    const float* cw2  = (const float*)d_in[16];
    const float* aw   = (const float*)d_in[17];
    const float* ab   = (const float*)d_in[18];
    /* d_in[19] rows, d_in[20] cols: structure known analytically */

    const int B = in_sizes[0];
    const size_t smem = (size_t)SMEM_FLOATS * sizeof(float);
    cudaFuncSetAttribute(egnn_kernel, cudaFuncAttributeMaxDynamicSharedMemorySize, (int)smem);
    egnn_kernel<<<B, NTHREADS, smem>>>(t, x, embW, embb, ew1, eb1, ew2, eb2,
                                       nw1, nb1, nw2, nb2, cw1, cb1, cw2, aw, ab,
                                       (float*)d_out);
}

// round 5
// speedup vs baseline: 1.6395x; 1.6395x over previous
#include <cuda_runtime.h>
#include <math.h>

#define PN 22
#define DN 3
#define HN 64
#define LN 5
#define NWARP 11
#define NTHREADS 352
#define CRC 3.0f       /* 15.0 / 5 layers */
#define LOG2M 7.0f

typedef unsigned long long ull;

/* ---- shared memory layout (floats) ---- */
constexpr int OFF_EW1 = 0;                     /* 130*64 = 8320 */
constexpr int OFF_EW2 = 8320;                  /* 64*64 */
constexpr int OFF_NW1 = 12416;                 /* 128*64 */
constexpr int OFF_NW2 = 20608;                 /* 64*64 */
constexpr int OFF_CW1 = 24704;                 /* 64*64 */
constexpr int OFF_CW2 = 28800;                 /* 64 */
constexpr int OFF_AW  = 28864;
constexpr int OFF_EB1 = 28928;
constexpr int OFF_EB2 = 28992;
constexpr int OFF_NB1 = 29056;
constexpr int OFF_NB2 = 29120;
constexpr int OFF_CB1 = 29184;
constexpr int OFF_H   = 29248;                 /* 22*64 */
constexpr int OFF_HR  = 30656;                 /* 22*64 */
constexpr int OFF_HC  = 32064;                 /* 22*64 */
constexpr int OFF_EA  = 33472;                 /* 22*22=484, pad to 488 */
constexpr int OFF_WB  = 33960;                 /* 11 warps * 8 edges * 64 ull = 11264 floats */
constexpr int OFF_CRD = 45224;                 /* 66 -> pad 68 */
constexpr int OFF_CR0 = 45292;
constexpr int OFF_VEL = 45360;
constexpr int OFF_MEAN = 45428;
constexpr int OFF_AB  = 45432;
constexpr int SMEM_FLOATS = 45436;             /* 181,744 bytes */

__device__ __forceinline__ float siluf(float v) { return v / (1.f + __expf(-v)); }
__device__ __forceinline__ float sigmf_(float v) { return 1.f / (1.f + __expf(-v)); }

__device__ __forceinline__ void ffma2(ull& d, ull a, ull b) {
    asm("fma.rn.f32x2 %0, %1, %2, %0;" : "+l"(d) : "l"(a), "l"(b));
}
__device__ __forceinline__ ull add2(ull a, ull b) {
    ull r; asm("add.rn.f32x2 %0, %1, %2;" : "=l"(r) : "l"(a), "l"(b)); return r;
}
__device__ __forceinline__ ull pack2(float x, float y) {
    ull r; asm("mov.b64 %0, {%1, %2};" : "=l"(r) : "f"(x), "f"(y)); return r;
}
__device__ __forceinline__ void unpack2(ull v, float& x, float& y) {
    asm("mov.b64 {%0, %1}, %2;" : "=f"(x), "=f"(y) : "l"(v));
}

/* 8-edge-batched GEMV with packed FFMA2.
   Wm: 64x64 row-major (floats). act: 8 rows of 64 ull, each ull = {a,a} duplicated.
   u[e] accumulates output cols (2*lane, 2*lane+1) as f32x2. */
__device__ __forceinline__ void gemv8(const float* __restrict__ Wm,
                                      const ull* __restrict__ act,
                                      const int lane, ull u[8])
{
#pragma unroll 8
    for (int k = 0; k < HN; k += 2) {
        const ull w0 = *(const ull*)&Wm[k * HN + 2 * lane];
        const ull w1 = *(const ull*)&Wm[(k + 1) * HN + 2 * lane];
#pragma unroll
        for (int e = 0; e < 8; ++e) {
            const ulonglong2 a = *(const ulonglong2*)&act[e * HN + k];
            ffma2(u[e], a.x, w0);
            ffma2(u[e], a.y, w1);
        }
    }
}

__global__ __launch_bounds__(NTHREADS, 1)
void egnn_kernel(const float* __restrict__ t, const float* __restrict__ x,
                 const float* __restrict__ embW, const float* __restrict__ embb,
                 const float* __restrict__ ew1, const float* __restrict__ eb1,
                 const float* __restrict__ ew2, const float* __restrict__ eb2,
                 const float* __restrict__ nw1, const float* __restrict__ nb1,
                 const float* __restrict__ nw2, const float* __restrict__ nb2,
                 const float* __restrict__ cw1, const float* __restrict__ cb1,
                 const float* __restrict__ cw2, const float* __restrict__ aw,
                 const float* __restrict__ ab, float* __restrict__ out)
{
    extern __shared__ float sm[];
    const int tid = threadIdx.x;
    const int b = blockIdx.x;
    const int w = tid >> 5;
    const int lane = tid & 31;

    /* ---- init: coords, h ---- */
    for (int idx = tid; idx < PN * DN; idx += NTHREADS) {
        const float c = x[b * (PN * DN) + idx];
        sm[OFF_CRD + idx] = c;
        sm[OFF_CR0 + idx] = c;
    }
    const float tb = t[b];
    for (int idx = tid; idx < PN * HN; idx += NTHREADS) {
        const int i = idx >> 6, o = idx & 63;
        sm[OFF_H + idx] = embW[i * HN + o] + tb * embW[22 * HN + o]
                        + LOG2M * embW[23 * HN + o] + embb[o];
    }
    __syncthreads();
    /* edge_attr = initial squared distances */
    for (int idx = tid; idx < PN * PN; idx += NTHREADS) {
        const int i = idx / PN, j = idx % PN;
        const float dx = sm[OFF_CRD + i * 3 + 0] - sm[OFF_CRD + j * 3 + 0];
        const float dy = sm[OFF_CRD + i * 3 + 1] - sm[OFF_CRD + j * 3 + 1];
        const float dz = sm[OFF_CRD + i * 3 + 2] - sm[OFF_CRD + j * 3 + 2];
        sm[OFF_EA + idx] = dx * dx + dy * dy + dz * dz;
    }
    /* barrier after weight staging below orders EA before use */

    ull* const wbu = (ull*)(sm + OFF_WB) + (size_t)w * 8 * HN;

    for (int l = 0; l < LN; ++l) {
        /* ---- stage this layer's weights into shared ---- */
        {
            const float* s1 = ew1 + l * 130 * 64;
            for (int q = tid; q < 130 * 64; q += NTHREADS) sm[OFF_EW1 + q] = s1[q];
            const float* s2 = ew2 + l * 4096;
            for (int q = tid; q < 4096; q += NTHREADS) sm[OFF_EW2 + q] = s2[q];
            const float* s3 = nw1 + l * 8192;
            for (int q = tid; q < 8192; q += NTHREADS) sm[OFF_NW1 + q] = s3[q];
            const float* s4 = nw2 + l * 4096;
            for (int q = tid; q < 4096; q += NTHREADS) sm[OFF_NW2 + q] = s4[q];
            const float* s5 = cw1 + l * 4096;
            for (int q = tid; q < 4096; q += NTHREADS) sm[OFF_CW1 + q] = s5[q];
            if (tid < 64) {
                sm[OFF_CW2 + tid] = cw2[l * 64 + tid];
                sm[OFF_AW + tid]  = aw[l * 64 + tid];
                sm[OFF_EB1 + tid] = eb1[l * 64 + tid];
                sm[OFF_EB2 + tid] = eb2[l * 64 + tid];
                sm[OFF_NB1 + tid] = nb1[l * 64 + tid];
                sm[OFF_NB2 + tid] = nb2[l * 64 + tid];
                sm[OFF_CB1 + tid] = cb1[l * 64 + tid];
            }
            if (tid == 0) sm[OFF_AB] = ab[l];
        }
        __syncthreads();

        /* ---- phase 1: Hr = h@W1[0:64], Hc = h@W1[64:128] (packed) ---- */
#pragma unroll
        for (int nn = 0; nn < 2; ++nn) {
            const int i = w * 2 + nn;
            ull r2 = 0ull, c2 = 0ull;
#pragma unroll 8
            for (int k = 0; k < HN; ++k) {
                const float a = sm[OFF_H + i * HN + k];
                const ull ap = pack2(a, a);
                ffma2(r2, ap, *(const ull*)&sm[OFF_EW1 + k * HN + 2 * lane]);
                ffma2(c2, ap, *(const ull*)&sm[OFF_EW1 + (64 + k) * HN + 2 * lane]);
            }
            *(ull*)&sm[OFF_HR + i * HN + 2 * lane] = r2;
            *(ull*)&sm[OFF_HC + i * HN + 2 * lane] = c2;
        }
        __syncthreads();

        /* ---- phase 2: edges, 8 at a time per warp ---- */
        float aggL[2][2];
        float dcd[2][3];
        for (int nn = 0; nn < 2; ++nn) {
            const int i = w * 2 + nn;
            float agg0 = 0.f, agg1 = 0.f, dc0 = 0.f, dc1 = 0.f, dc2 = 0.f;
            const float cix = sm[OFF_CRD + i * 3 + 0];
            const float ciy = sm[OFF_CRD + i * 3 + 1];
            const float ciz = sm[OFF_CRD + i * 3 + 2];
            const ull hrp   = *(const ull*)&sm[OFF_HR + i * HN + 2 * lane];
            const ull w128p = *(const ull*)&sm[OFF_EW1 + 128 * HN + 2 * lane];
            const ull w129p = *(const ull*)&sm[OFF_EW1 + 129 * HN + 2 * lane];
            const ull b1p   = *(const ull*)&sm[OFF_EB1 + 2 * lane];
            const ull b2p   = *(const ull*)&sm[OFF_EB2 + 2 * lane];
            const ull cbp   = *(const ull*)&sm[OFF_CB1 + 2 * lane];
            const float aw0  = sm[OFF_AW + 2 * lane];
            const float aw1  = sm[OFF_AW + 2 * lane + 1];
            const float cw20 = sm[OFF_CW2 + 2 * lane];
            const float cw21 = sm[OFF_CW2 + 2 * lane + 1];
            const float abv  = sm[OFF_AB];

            for (int g = 0; g < 3; ++g) {
                float ndx[8], ndy[8], ndz[8];
                /* stage t1 = silu(e_in @ ew1 + eb1), duplicated {v,v} */
#pragma unroll
                for (int e = 0; e < 8; ++e) {
                    const int jraw = g * 8 + e;
                    int j = (jraw < i) ? jraw : jraw + 1;
                    if (j >= PN) j = i;               /* dummy self-edge */
                    const float dx = cix - sm[OFF_CRD + j * 3 + 0];
                    const float dy = ciy - sm[OFF_CRD + j * 3 + 1];
                    const float dz = ciz - sm[OFF_CRD + j * 3 + 2];
                    const float radial = dx * dx + dy * dy + dz * dz;
                    const float inv = 1.f / (sqrtf(radial) + 1.f);
                    ndx[e] = dx * inv; ndy[e] = dy * inv; ndz[e] = dz * inv;
                    const float eav = sm[OFF_EA + i * PN + j];
                    ull p = add2(add2(hrp, *(const ull*)&sm[OFF_HC + j * HN + 2 * lane]), b1p);
                    ffma2(p, pack2(radial, radial), w128p);
                    ffma2(p, pack2(eav, eav), w129p);
                    float p0, p1; unpack2(p, p0, p1);
                    const float v0 = siluf(p0), v1 = siluf(p1);
                    wbu[e * HN + 2 * lane]     = pack2(v0, v0);
                    wbu[e * HN + 2 * lane + 1] = pack2(v1, v1);
                }
                __syncwarp();

                /* GEMV2: m = silu(t1 @ ew2 + eb2) */
                ull u[8];
#pragma unroll
                for (int e = 0; e < 8; ++e) u[e] = b2p;
                gemv8(&sm[OFF_EW2], wbu, lane, u);

                float m0[8], m1[8], part[8];
#pragma unroll
                for (int e = 0; e < 8; ++e) {
                    float x0, x1; unpack2(u[e], x0, x1);
                    m0[e] = siluf(x0); m1[e] = siluf(x1);
                    part[e] = m0[e] * aw0 + m1[e] * aw1;
                }
#pragma unroll
                for (int off = 16; off; off >>= 1)
#pragma unroll
                    for (int e = 0; e < 8; ++e)
                        part[e] += __shfl_xor_sync(0xffffffffu, part[e], off);
#pragma unroll
                for (int e = 0; e < 8; ++e) {
                    const float gate = sigmf_(part[e] + abv);
                    m0[e] *= gate; m1[e] *= gate;
                }
                __syncwarp();   /* gemv2 reads of t1 complete */
#pragma unroll
                for (int e = 0; e < 8; ++e) {
                    wbu[e * HN + 2 * lane]     = pack2(m0[e], m0[e]);
                    wbu[e * HN + 2 * lane + 1] = pack2(m1[e], m1[e]);
                }
                __syncwarp();

                /* GEMV3: c1 = silu(m @ cw1 + cb1); scal = tanh(c1 @ cw2)*CR */
                ull q[8];
#pragma unroll
                for (int e = 0; e < 8; ++e) q[e] = cbp;
                gemv8(&sm[OFF_CW1], wbu, lane, q);

                float s[8];
#pragma unroll
                for (int e = 0; e < 8; ++e) {
                    float x0, x1; unpack2(q[e], x0, x1);
                    s[e] = siluf(x0) * cw20 + siluf(x1) * cw21;
                }
#pragma unroll
                for (int off = 16; off; off >>= 1)
#pragma unroll
                    for (int e = 0; e < 8; ++e)
                        s[e] += __shfl_xor_sync(0xffffffffu, s[e], off);
#pragma unroll
                for (int e = 0; e < 8; ++e) {
                    const float scal = tanhf(s[e]) * CRC;
                    dc0 += ndx[e] * scal;
                    dc1 += ndy[e] * scal;
                    dc2 += ndz[e] * scal;
                    if (g * 8 + e < PN - 1) { agg0 += m0[e]; agg1 += m1[e]; }
                }
                __syncwarp();   /* reads of m done before next group rewrites wbu */
            }
            aggL[nn][0] = agg0; aggL[nn][1] = agg1;
            dcd[nn][0] = dc0; dcd[nn][1] = dc1; dcd[nn][2] = dc2;
        }
        __syncthreads();   /* all reads of coord/Hr/Hc complete */

        /* ---- phase 3: coord update + node MLP (owner warp, no atomics) ---- */
        float* const wbf = (float*)wbu;
#pragma unroll
        for (int nn = 0; nn < 2; ++nn) {
            const int i = w * 2 + nn;
            if (lane == 0) {
                sm[OFF_CRD + i * 3 + 0] += dcd[nn][0];
                sm[OFF_CRD + i * 3 + 1] += dcd[nn][1];
                sm[OFF_CRD + i * 3 + 2] += dcd[nn][2];
            }
            wbf[2 * lane] = aggL[nn][0];
            wbf[2 * lane + 1] = aggL[nn][1];
            __syncwarp();
            ull g2 = *(const ull*)&sm[OFF_NB1 + 2 * lane];
#pragma unroll 8
            for (int k = 0; k < HN; ++k) {
                const float a = sm[OFF_H + i * HN + k];
                ffma2(g2, pack2(a, a), *(const ull*)&sm[OFF_NW1 + k * HN + 2 * lane]);
            }
#pragma unroll 8
            for (int k = 0; k < HN; ++k) {
                const float a = wbf[k];
                ffma2(g2, pack2(a, a), *(const ull*)&sm[OFF_NW1 + (HN + k) * HN + 2 * lane]);
            }
            float g0, g1; unpack2(g2, g0, g1);
            g0 = siluf(g0); g1 = siluf(g1);
            __syncwarp();
            wbf[2 * lane] = g0; wbf[2 * lane + 1] = g1;
            __syncwarp();
            ull o2 = *(const ull*)&sm[OFF_NB2 + 2 * lane];
#pragma unroll 8
            for (int k = 0; k < HN; ++k) {
                const float a = wbf[k];
                ffma2(o2, pack2(a, a), *(const ull*)&sm[OFF_NW2 + k * HN + 2 * lane]);
            }
            float o0, o1; unpack2(o2, o0, o1);
            sm[OFF_H + i * HN + 2 * lane]     += o0;
            sm[OFF_H + i * HN + 2 * lane + 1] += o1;
            __syncwarp();
        }
        __syncthreads();
    } /* layer loop */

    /* ---- velocity + mean removal ---- */
    for (int idx = tid; idx < PN * DN; idx += NTHREADS)
        sm[OFF_VEL + idx] = sm[OFF_CRD + idx] - sm[OFF_CR0 + idx];
    __syncthreads();
    if (tid < DN) {
        float s = 0.f;
        for (int i = 0; i < PN; ++i) s += sm[OFF_VEL + i * 3 + tid];
        sm[OFF_MEAN + tid] = s * (1.f / PN);
    }
    __syncthreads();
    for (int idx = tid; idx < PN * DN; idx += NTHREADS)
        out[b * (PN * DN) + idx] = sm[OFF_VEL + idx] - sm[OFF_MEAN + idx % 3];
}

extern "C" void kernel_launch(void* const* d_in, const int* in_sizes, int n_in,
                              void* d_out, int out_size)
{
    const float* t    = (const float*)d_in[0];
    const float* x    = (const float*)d_in[1];
    const float* embW = (const float*)d_in[2];
    const float* embb = (const float*)d_in[3];
    /* d_in[4] out_W, d_in[5] out_b: dead code (output depends only on coords) */
    const float* ew1  = (const float*)d_in[6];
    const float* eb1  = (const float*)d_in[7];
    const float* ew2  = (const float*)d_in[8];
    const float* eb2  = (const float*)d_in[9];
    const float* nw1  = (const float*)d_in[10];
    const float* nb1  = (const float*)d_in[11];
    const float* nw2  = (const float*)d_in[12];
    const float* nb2  = (const float*)d_in[13];
    const float* cw1  = (const float*)d_in[14];
    const float* cb1  = (const float*)d_in[15];
    const float* cw2  = (const float*)d_in[16];
    const float* aw   = (const float*)d_in[17];
    const float* ab   = (const float*)d_in[18];
    /* d_in[19] rows, d_in[20] cols: structure known analytically */

    const int B = in_sizes[0];
    const size_t smem = (size_t)SMEM_FLOATS * sizeof(float);
    cudaFuncSetAttribute(egnn_kernel, cudaFuncAttributeMaxDynamicSharedMemorySize, (int)smem);
    egnn_kernel<<<B, NTHREADS, smem>>>(t, x, embW, embb, ew1, eb1, ew2, eb2,
                                       nw1, nb1, nw2, nb2, cw1, cb1, cw2, aw, ab,
                                       (float*)d_out);
}

// round 6
// speedup vs baseline: 1.9678x; 1.2002x over previous
#include <cuda_runtime.h>
#include <math.h>

#define PN 22
#define DN 3
#define HN 64
#define LN 5
#define NWARP 11
#define NTHREADS 352
#define CRC 3.0f       /* 15.0 / 5 layers */
#define LOG2M 7.0f

typedef unsigned long long ull;

/* ---- shared memory layout (floats) ---- */
constexpr int OFF_EW1 = 0;                     /* 130*64 = 8320 */
constexpr int OFF_EW2 = 8320;                  /* 64*64 */
constexpr int OFF_NW1 = 12416;                 /* 128*64 */
constexpr int OFF_NW2 = 20608;                 /* 64*64 */
constexpr int OFF_CW1 = 24704;                 /* 64*64 */
constexpr int OFF_CW2 = 28800;                 /* 64 */
constexpr int OFF_AW  = 28864;
constexpr int OFF_EB1 = 28928;
constexpr int OFF_EB2 = 28992;
constexpr int OFF_NB1 = 29056;
constexpr int OFF_NB2 = 29120;
constexpr int OFF_CB1 = 29184;
constexpr int OFF_H   = 29248;                 /* 22*64 */
constexpr int OFF_HR  = 30656;                 /* 22*64 */
constexpr int OFF_HC  = 32064;                 /* 22*64 */
constexpr int OFF_EA  = 33472;                 /* 22*22=484, pad 488 */
constexpr int OFF_WB  = 33960;                 /* 11 warps * 16 edges * 64 ull = 22528 floats */
constexpr int OFF_CRD = 56488;                 /* 66 -> pad 68 */
constexpr int OFF_CR0 = 56556;
constexpr int OFF_VEL = 56624;
constexpr int OFF_MEAN = 56692;
constexpr int OFF_AB  = 56696;
constexpr int SMEM_FLOATS = 56700;             /* 226,800 bytes */

__device__ __forceinline__ float siluf(float v) { return v / (1.f + __expf(-v)); }
__device__ __forceinline__ float sigmf_(float v) { return 1.f / (1.f + __expf(-v)); }

__device__ __forceinline__ void ffma2(ull& d, ull a, ull b) {
    asm("fma.rn.f32x2 %0, %1, %2, %0;" : "+l"(d) : "l"(a), "l"(b));
}
__device__ __forceinline__ ull add2(ull a, ull b) {
    ull r; asm("add.rn.f32x2 %0, %1, %2;" : "=l"(r) : "l"(a), "l"(b)); return r;
}
__device__ __forceinline__ ull pack2(float x, float y) {
    ull r; asm("mov.b64 %0, {%1, %2};" : "=l"(r) : "f"(x), "f"(y)); return r;
}
__device__ __forceinline__ void unpack2(ull v, float& x, float& y) {
    asm("mov.b64 {%0, %1}, %2;" : "=f"(x), "=f"(y) : "l"(v));
}

/* 16-edge, 4-col/lane GEMV with packed FFMA2.
   Wm: 64x64 row-major floats. act: this half-warp's 8 edges, 64 duplicated
   ulls each. Lane (c = lane&15) accumulates output cols 4c..4c+3 into
   u[e][0]={4c,4c+1}, u[e][1]={4c+2,4c+3}. */
__device__ __forceinline__ void gemv16(const float* __restrict__ Wm,
                                       const ull* __restrict__ act,
                                       const int c4, ull u[8][2])
{
#pragma unroll 8
    for (int k = 0; k < HN; k += 2) {
        const ulonglong2 w0 = *(const ulonglong2*)&Wm[k * HN + c4];
        const ulonglong2 w1 = *(const ulonglong2*)&Wm[(k + 1) * HN + c4];
#pragma unroll
        for (int e = 0; e < 8; ++e) {
            const ulonglong2 a = *(const ulonglong2*)&act[e * HN + k];
            ffma2(u[e][0], a.x, w0.x);
            ffma2(u[e][1], a.x, w0.y);
            ffma2(u[e][0], a.y, w1.x);
            ffma2(u[e][1], a.y, w1.y);
        }
    }
}

__global__ __launch_bounds__(NTHREADS, 1)
void egnn_kernel(const float* __restrict__ t, const float* __restrict__ x,
                 const float* __restrict__ embW, const float* __restrict__ embb,
                 const float* __restrict__ ew1, const float* __restrict__ eb1,
                 const float* __restrict__ ew2, const float* __restrict__ eb2,
                 const float* __restrict__ nw1, const float* __restrict__ nb1,
                 const float* __restrict__ nw2, const float* __restrict__ nb2,
                 const float* __restrict__ cw1, const float* __restrict__ cb1,
                 const float* __restrict__ cw2, const float* __restrict__ aw,
                 const float* __restrict__ ab, float* __restrict__ out)
{
    extern __shared__ float sm[];
    const int tid = threadIdx.x;
    const int b = blockIdx.x;
    const int w = tid >> 5;
    const int lane = tid & 31;
    const int hw = lane >> 4;        /* half-warp id: edge subset   */
    const int c4 = (lane & 15) * 4;  /* 4 output cols per lane      */

    /* ---- init: coords, h ---- */
    for (int idx = tid; idx < PN * DN; idx += NTHREADS) {
        const float c = x[b * (PN * DN) + idx];
        sm[OFF_CRD + idx] = c;
        sm[OFF_CR0 + idx] = c;
    }
    const float tb = t[b];
    for (int idx = tid; idx < PN * HN; idx += NTHREADS) {
        const int i = idx >> 6, o = idx & 63;
        sm[OFF_H + idx] = embW[i * HN + o] + tb * embW[22 * HN + o]
                        + LOG2M * embW[23 * HN + o] + embb[o];
    }
    __syncthreads();
    /* edge_attr = initial squared distances */
    for (int idx = tid; idx < PN * PN; idx += NTHREADS) {
        const int i = idx / PN, j = idx % PN;
        const float dx = sm[OFF_CRD + i * 3 + 0] - sm[OFF_CRD + j * 3 + 0];
        const float dy = sm[OFF_CRD + i * 3 + 1] - sm[OFF_CRD + j * 3 + 1];
        const float dz = sm[OFF_CRD + i * 3 + 2] - sm[OFF_CRD + j * 3 + 2];
        sm[OFF_EA + idx] = dx * dx + dy * dy + dz * dz;
    }
    /* barrier after weight staging below orders EA before use */

    ull* const wbu = (ull*)(sm + OFF_WB) + (size_t)w * 16 * HN;   /* 16 edges */
    ull* const act = wbu + hw * 8 * HN;                           /* my half  */

    for (int l = 0; l < LN; ++l) {
        /* ---- stage this layer's weights into shared ---- */
        {
            const float* s1 = ew1 + l * 130 * 64;
            for (int q = tid; q < 130 * 64; q += NTHREADS) sm[OFF_EW1 + q] = s1[q];
            const float* s2 = ew2 + l * 4096;
            for (int q = tid; q < 4096; q += NTHREADS) sm[OFF_EW2 + q] = s2[q];
            const float* s3 = nw1 + l * 8192;
            for (int q = tid; q < 8192; q += NTHREADS) sm[OFF_NW1 + q] = s3[q];
            const float* s4 = nw2 + l * 4096;
            for (int q = tid; q < 4096; q += NTHREADS) sm[OFF_NW2 + q] = s4[q];
            const float* s5 = cw1 + l * 4096;
            for (int q = tid; q < 4096; q += NTHREADS) sm[OFF_CW1 + q] = s5[q];
            if (tid < 64) {
                sm[OFF_CW2 + tid] = cw2[l * 64 + tid];
                sm[OFF_AW + tid]  = aw[l * 64 + tid];
                sm[OFF_EB1 + tid] = eb1[l * 64 + tid];
                sm[OFF_EB2 + tid] = eb2[l * 64 + tid];
                sm[OFF_NB1 + tid] = nb1[l * 64 + tid];
                sm[OFF_NB2 + tid] = nb2[l * 64 + tid];
                sm[OFF_CB1 + tid] = cb1[l * 64 + tid];
            }
            if (tid == 0) sm[OFF_AB] = ab[l];
        }
        __syncthreads();

        /* ---- phase 1: Hr = h@W1[0:64], Hc = h@W1[64:128] (2-col layout) ---- */
#pragma unroll
        for (int nn = 0; nn < 2; ++nn) {
            const int i = w * 2 + nn;
            ull r2 = 0ull, c2 = 0ull;
#pragma unroll 8
            for (int k = 0; k < HN; ++k) {
                const float a = sm[OFF_H + i * HN + k];
                const ull ap = pack2(a, a);
                ffma2(r2, ap, *(const ull*)&sm[OFF_EW1 + k * HN + 2 * lane]);
                ffma2(c2, ap, *(const ull*)&sm[OFF_EW1 + (64 + k) * HN + 2 * lane]);
            }
            *(ull*)&sm[OFF_HR + i * HN + 2 * lane] = r2;
            *(ull*)&sm[OFF_HC + i * HN + 2 * lane] = c2;
        }
        __syncthreads();

        /* ---- phase 2: 42 edges of this warp's node pair, 16 per pass ---- */
        /* hoisted per-col constants (cols c4..c4+3) */
        const ulonglong2 w128q = *(const ulonglong2*)&sm[OFF_EW1 + 128 * HN + c4];
        const ulonglong2 w129q = *(const ulonglong2*)&sm[OFF_EW1 + 129 * HN + c4];
        const ulonglong2 b1q   = *(const ulonglong2*)&sm[OFF_EB1 + c4];
        const ulonglong2 b2q   = *(const ulonglong2*)&sm[OFF_EB2 + c4];
        const ulonglong2 cbq   = *(const ulonglong2*)&sm[OFF_CB1 + c4];
        const float4 aw4  = *(const float4*)&sm[OFF_AW + c4];
        const float4 cw4  = *(const float4*)&sm[OFF_CW2 + c4];
        const float abv   = sm[OFF_AB];

        float dc[2][3] = {{0.f,0.f,0.f},{0.f,0.f,0.f}};
        float agg[2][4] = {{0.f,0.f,0.f,0.f},{0.f,0.f,0.f,0.f}};

#pragma unroll 1
        for (int p = 0; p < 3; ++p) {
            float nd[8][3];
            int   nsel[8];
            float vld[8];
            /* setup: build t1 = silu(e_in @ ew1 + eb1) duplicated in act */
#pragma unroll
            for (int e = 0; e < 8; ++e) {
                const int eg = p * 16 + hw * 8 + e;
                const int n = (eg < 21) ? 0 : 1;
                const int i = 2 * w + n;
                const int r = eg - n * 21;
                int j = (r < i) ? r : r + 1;
                const float v = (j < PN) ? 1.f : 0.f;
                if (j >= PN) j = i;            /* dummy pad edge */
                nsel[e] = n; vld[e] = v;
                const float dx = sm[OFF_CRD + i * 3 + 0] - sm[OFF_CRD + j * 3 + 0];
                const float dy = sm[OFF_CRD + i * 3 + 1] - sm[OFF_CRD + j * 3 + 1];
                const float dz = sm[OFF_CRD + i * 3 + 2] - sm[OFF_CRD + j * 3 + 2];
                const float radial = dx * dx + dy * dy + dz * dz;
                const float inv = 1.f / (sqrtf(radial) + 1.f);
                nd[e][0] = dx * inv; nd[e][1] = dy * inv; nd[e][2] = dz * inv;
                const float eav = sm[OFF_EA + i * PN + j];
                const ulonglong2 hrq = *(const ulonglong2*)&sm[OFF_HR + i * HN + c4];
                const ulonglong2 hcq = *(const ulonglong2*)&sm[OFF_HC + j * HN + c4];
                const ull rad2 = pack2(radial, radial);
                const ull ea2  = pack2(eav, eav);
                ull p01 = add2(add2(hrq.x, hcq.x), b1q.x);
                ull p23 = add2(add2(hrq.y, hcq.y), b1q.y);
                ffma2(p01, rad2, w128q.x); ffma2(p23, rad2, w128q.y);
                ffma2(p01, ea2,  w129q.x); ffma2(p23, ea2,  w129q.y);
                float t0, t1v, t2, t3;
                unpack2(p01, t0, t1v); unpack2(p23, t2, t3);
                t0 = siluf(t0); t1v = siluf(t1v); t2 = siluf(t2); t3 = siluf(t3);
                ulonglong2 s0; s0.x = pack2(t0, t0); s0.y = pack2(t1v, t1v);
                ulonglong2 s1; s1.x = pack2(t2, t2); s1.y = pack2(t3, t3);
                *(ulonglong2*)&act[e * HN + c4]     = s0;
                *(ulonglong2*)&act[e * HN + c4 + 2] = s1;
            }
            __syncwarp();

            /* GEMV2: m = silu(t1 @ ew2 + eb2), attention gate, agg */
            ull u[8][2];
#pragma unroll
            for (int e = 0; e < 8; ++e) { u[e][0] = b2q.x; u[e][1] = b2q.y; }
            gemv16(&sm[OFF_EW2], act, c4, u);

            float m[8][4], part[8];
#pragma unroll
            for (int e = 0; e < 8; ++e) {
                unpack2(u[e][0], m[e][0], m[e][1]);
                unpack2(u[e][1], m[e][2], m[e][3]);
                m[e][0] = siluf(m[e][0]); m[e][1] = siluf(m[e][1]);
                m[e][2] = siluf(m[e][2]); m[e][3] = siluf(m[e][3]);
                part[e] = m[e][0] * aw4.x + m[e][1] * aw4.y
                        + m[e][2] * aw4.z + m[e][3] * aw4.w;
            }
#pragma unroll
            for (int off = 1; off < 16; off <<= 1)
#pragma unroll
                for (int e = 0; e < 8; ++e)
                    part[e] += __shfl_xor_sync(0xffffffffu, part[e], off);
#pragma unroll
            for (int e = 0; e < 8; ++e) {
                const float gate = sigmf_(part[e] + abv);
                m[e][0] *= gate; m[e][1] *= gate; m[e][2] *= gate; m[e][3] *= gate;
                const float vm = vld[e];
                if (nsel[e] == 0) {
                    agg[0][0] += m[e][0] * vm; agg[0][1] += m[e][1] * vm;
                    agg[0][2] += m[e][2] * vm; agg[0][3] += m[e][3] * vm;
                } else {
                    agg[1][0] += m[e][0] * vm; agg[1][1] += m[e][1] * vm;
                    agg[1][2] += m[e][2] * vm; agg[1][3] += m[e][3] * vm;
                }
            }
            __syncwarp();
#pragma unroll
            for (int e = 0; e < 8; ++e) {
                ulonglong2 s0; s0.x = pack2(m[e][0], m[e][0]); s0.y = pack2(m[e][1], m[e][1]);
                ulonglong2 s1; s1.x = pack2(m[e][2], m[e][2]); s1.y = pack2(m[e][3], m[e][3]);
                *(ulonglong2*)&act[e * HN + c4]     = s0;
                *(ulonglong2*)&act[e * HN + c4 + 2] = s1;
            }
            __syncwarp();

            /* GEMV3: c1 = silu(m @ cw1 + cb1); scal = tanh(c1 @ cw2)*CR */
            ull q[8][2];
#pragma unroll
            for (int e = 0; e < 8; ++e) { q[e][0] = cbq.x; q[e][1] = cbq.y; }
            gemv16(&sm[OFF_CW1], act, c4, q);

            float s[8];
#pragma unroll
            for (int e = 0; e < 8; ++e) {
                float x0, x1, x2, x3;
                unpack2(q[e][0], x0, x1); unpack2(q[e][1], x2, x3);
                s[e] = siluf(x0) * cw4.x + siluf(x1) * cw4.y
                     + siluf(x2) * cw4.z + siluf(x3) * cw4.w;
            }
#pragma unroll
            for (int off = 1; off < 16; off <<= 1)
#pragma unroll
                for (int e = 0; e < 8; ++e)
                    s[e] += __shfl_xor_sync(0xffffffffu, s[e], off);
#pragma unroll
            for (int e = 0; e < 8; ++e) {
                const float scal = tanhf(s[e]) * CRC;
                if (nsel[e] == 0) {
                    dc[0][0] += nd[e][0] * scal;
                    dc[0][1] += nd[e][1] * scal;
                    dc[0][2] += nd[e][2] * scal;
                } else {
                    dc[1][0] += nd[e][0] * scal;
                    dc[1][1] += nd[e][1] * scal;
                    dc[1][2] += nd[e][2] * scal;
                }
            }
            __syncwarp();   /* gemv3 reads done before next pass rewrites act */
        }

        /* combine half-warps (other half processed disjoint edges) */
#pragma unroll
        for (int n = 0; n < 2; ++n) {
#pragma unroll
            for (int d = 0; d < 3; ++d)
                dc[n][d] += __shfl_xor_sync(0xffffffffu, dc[n][d], 16);
#pragma unroll
            for (int cc = 0; cc < 4; ++cc)
                agg[n][cc] += __shfl_xor_sync(0xffffffffu, agg[n][cc], 16);
        }
        /* stage agg into wbf[n*64 + col] for phase 3 */
        float* const wbf = (float*)wbu;
        if (hw == 0) {
#pragma unroll
            for (int n = 0; n < 2; ++n) {
                wbf[n * HN + c4]     = agg[n][0];
                wbf[n * HN + c4 + 1] = agg[n][1];
                wbf[n * HN + c4 + 2] = agg[n][2];
                wbf[n * HN + c4 + 3] = agg[n][3];
            }
        }
        __syncthreads();   /* all reads of coord/Hr/Hc complete; agg staged */

        /* ---- phase 3: coord update + node MLP (owner warp, 2-col layout) ---- */
#pragma unroll
        for (int nn = 0; nn < 2; ++nn) {
            const int i = w * 2 + nn;
            if (lane == 0) {
                sm[OFF_CRD + i * 3 + 0] += dc[nn][0];
                sm[OFF_CRD + i * 3 + 1] += dc[nn][1];
                sm[OFF_CRD + i * 3 + 2] += dc[nn][2];
            }
            ull g2 = *(const ull*)&sm[OFF_NB1 + 2 * lane];
#pragma unroll 8
            for (int k = 0; k < HN; ++k) {
                const float a = sm[OFF_H + i * HN + k];
                ffma2(g2, pack2(a, a), *(const ull*)&sm[OFF_NW1 + k * HN + 2 * lane]);
            }
#pragma unroll 8
            for (int k = 0; k < HN; ++k) {
                const float a = wbf[nn * HN + k];
                ffma2(g2, pack2(a, a), *(const ull*)&sm[OFF_NW1 + (HN + k) * HN + 2 * lane]);
            }
            float g0, g1; unpack2(g2, g0, g1);
            g0 = siluf(g0); g1 = siluf(g1);
            wbf[128 + nn * HN + 2 * lane] = g0;
            wbf[128 + nn * HN + 2 * lane + 1] = g1;
            __syncwarp();
            ull o2 = *(const ull*)&sm[OFF_NB2 + 2 * lane];
#pragma unroll 8
            for (int k = 0; k < HN; ++k) {
                const float a = wbf[128 + nn * HN + k];
                ffma2(o2, pack2(a, a), *(const ull*)&sm[OFF_NW2 + k * HN + 2 * lane]);
            }
            float o0, o1; unpack2(o2, o0, o1);
            sm[OFF_H + i * HN + 2 * lane]     += o0;
            sm[OFF_H + i * HN + 2 * lane + 1] += o1;
            __syncwarp();
        }
        __syncthreads();
    } /* layer loop */

    /* ---- velocity + mean removal ---- */
    for (int idx = tid; idx < PN * DN; idx += NTHREADS)
        sm[OFF_VEL + idx] = sm[OFF_CRD + idx] - sm[OFF_CR0 + idx];
    __syncthreads();
    if (tid < DN) {
        float s = 0.f;
        for (int i = 0; i < PN; ++i) s += sm[OFF_VEL + i * 3 + tid];
        sm[OFF_MEAN + tid] = s * (1.f / PN);
    }
    __syncthreads();
    for (int idx = tid; idx < PN * DN; idx += NTHREADS)
        out[b * (PN * DN) + idx] = sm[OFF_VEL + idx] - sm[OFF_MEAN + idx % 3];
}

extern "C" void kernel_launch(void* const* d_in, const int* in_sizes, int n_in,
                              void* d_out, int out_size)
{
    const float* t    = (const float*)d_in[0];
    const float* x    = (const float*)d_in[1];
    const float* embW = (const float*)d_in[2];
    const float* embb = (const float*)d_in[3];
    /* d_in[4] out_W, d_in[5] out_b: dead code (output depends only on coords) */
    const float* ew1  = (const float*)d_in[6];
    const float* eb1  = (const float*)d_in[7];
    const float* ew2  = (const float*)d_in[8];
    const float* eb2  = (const float*)d_in[9];
    const float* nw1  = (const float*)d_in[10];
    const float* nb1  = (const float*)d_in[11];
    const float* nw2  = (const float*)d_in[12];
    const float* nb2  = (const float*)d_in[13];
    const float* cw1  = (const float*)d_in[14];
    const float* cb1  = (const float*)d_in[15];
    const float* cw2  = (const float*)d_in[16];
    const float* aw   = (const float*)d_in[17];
    const float* ab   = (const float*)d_in[18];
    /* d_in[19] rows, d_in[20] cols: structure known analytically */

    const int B = in_sizes[0];
    const size_t smem = (size_t)SMEM_FLOATS * sizeof(float);
    cudaFuncSetAttribute(egnn_kernel, cudaFuncAttributeMaxDynamicSharedMemorySize, (int)smem);
    egnn_kernel<<<B, NTHREADS, smem>>>(t, x, embW, embb, ew1, eb1, ew2, eb2,
                                       nw1, nb1, nw2, nb2, cw1, cb1, cw2, aw, ab,
                                       (float*)d_out);
}

// round 9
// speedup vs baseline: 2.0012x; 1.0170x over previous
#include <cuda_runtime.h>
#include <math.h>

#define PN 22
#define DN 3
#define HN 64
#define LN 5
#define NWARP 22
#define NTHREADS 704
#define CRC 3.0f       /* 15.0 / 5 layers */
#define LOG2M 7.0f

typedef unsigned long long ull;

/* ---- shared memory layout (floats) ---- */
constexpr int OFF_EW2  = 0;        /* 64*64  */
constexpr int OFF_CW1  = 4096;     /* 64*64  */
constexpr int OFF_NW1  = 8192;     /* 128*64 */
constexpr int OFF_NW2  = 16384;    /* 64*64  */
constexpr int OFF_EW1R = 20480;    /* ew1 rows 128,129 -> 128 floats */
constexpr int OFF_EB1  = 20608;
constexpr int OFF_EB2  = 20672;
constexpr int OFF_NB1  = 20736;
constexpr int OFF_NB2  = 20800;
constexpr int OFF_CB1  = 20864;
constexpr int OFF_CW2  = 20928;
constexpr int OFF_AW   = 20992;
constexpr int OFF_AB   = 21056;    /* + pad */
constexpr int OFF_H    = 21060;    /* 2 * 22*64 */
constexpr int OFF_HR   = 23876;
constexpr int OFF_HC   = 26692;
constexpr int OFF_EA   = 29508;    /* 2 * 484 */
constexpr int OFF_CRD  = 30476;    /* 2 * 68 */
constexpr int OFF_CR0  = 30612;
constexpr int OFF_VEL  = 30748;
constexpr int OFF_MEAN = 30884;    /* 8 */
constexpr int OFF_WB   = 30892;    /* 22 warps * 8 edges * 64 ull = 22528 floats */
constexpr int SMEM_FLOATS = 53420; /* 213,680 bytes */

__device__ __forceinline__ float siluf(float v) { return v / (1.f + __expf(-v)); }
__device__ __forceinline__ float sigmf_(float v) { return 1.f / (1.f + __expf(-v)); }

__device__ __forceinline__ void ffma2(ull& d, ull a, ull b) {
    asm("fma.rn.f32x2 %0, %1, %2, %0;" : "+l"(d) : "l"(a), "l"(b));
}
__device__ __forceinline__ ull add2(ull a, ull b) {
    ull r; asm("add.rn.f32x2 %0, %1, %2;" : "=l"(r) : "l"(a), "l"(b)); return r;
}
__device__ __forceinline__ ull pack2(float x, float y) {
    ull r; asm("mov.b64 %0, {%1, %2};" : "=l"(r) : "f"(x), "f"(y)); return r;
}
__device__ __forceinline__ void unpack2(ull v, float& x, float& y) {
    asm("mov.b64 {%0, %1}, %2;" : "=f"(x), "=f"(y) : "l"(v));
}

/* 8-edge (4 per half-warp), 4-col/lane GEMV with packed FFMA2.
   Wm: 64x64 row-major floats. act: this half-warp's 4 edges, 64 duplicated
   ulls each. Lane (c4) accumulates output cols c4..c4+3. */
__device__ __forceinline__ void gemv4(const float* __restrict__ Wm,
                                      const ull* __restrict__ act,
                                      const int c4, ull u[4][2])
{
#pragma unroll 8
    for (int k = 0; k < HN; k += 2) {
        const ulonglong2 w0 = *(const ulonglong2*)&Wm[k * HN + c4];
        const ulonglong2 w1 = *(const ulonglong2*)&Wm[(k + 1) * HN + c4];
#pragma unroll
        for (int e = 0; e < 4; ++e) {
            const ulonglong2 a = *(const ulonglong2*)&act[e * HN + k];
            ffma2(u[e][0], a.x, w0.x);
            ffma2(u[e][1], a.x, w0.y);
            ffma2(u[e][0], a.y, w1.x);
            ffma2(u[e][1], a.y, w1.y);
        }
    }
}

__global__ __launch_bounds__(NTHREADS, 1)
void egnn_kernel(const float* __restrict__ t, const float* __restrict__ x,
                 const float* __restrict__ embW, const float* __restrict__ embb,
                 const float* __restrict__ ew1, const float* __restrict__ eb1,
                 const float* __restrict__ ew2, const float* __restrict__ eb2,
                 const float* __restrict__ nw1, const float* __restrict__ nb1,
                 const float* __restrict__ nw2, const float* __restrict__ nb2,
                 const float* __restrict__ cw1, const float* __restrict__ cb1,
                 const float* __restrict__ cw2, const float* __restrict__ aw,
                 const float* __restrict__ ab, float* __restrict__ out)
{
    extern __shared__ float sm[];
    const int tid = threadIdx.x;
    const int b0 = blockIdx.x * 2;       /* this block: molecules b0, b0+1 */
    const int w = tid >> 5;
    const int lane = tid & 31;
    const int hw = lane >> 4;            /* half-warp: edge subset          */
    const int c4 = (lane & 15) * 4;      /* 4 output cols per lane          */
    const int i = w;                     /* node owned by this warp (both mols) */

    /* ---- init: coords, h, edge_attr for both molecules ---- */
    for (int idx = tid; idx < 2 * PN * DN; idx += NTHREADS) {
        const int m = idx / 66, rem = idx - m * 66;
        const float c = x[(b0 + m) * 66 + rem];
        sm[OFF_CRD + m * 68 + rem] = c;
        sm[OFF_CR0 + m * 68 + rem] = c;
    }
    const float tA = t[b0], tB = t[b0 + 1];
    for (int idx = tid; idx < 2 * PN * HN; idx += NTHREADS) {
        const int m = idx / 1408, q = idx - m * 1408;
        const int ii = q >> 6, o = q & 63;
        const float tb = m ? tB : tA;
        sm[OFF_H + m * 1408 + q] = embW[ii * HN + o] + tb * embW[22 * HN + o]
                                 + LOG2M * embW[23 * HN + o] + embb[o];
    }
    __syncthreads();
    for (int idx = tid; idx < 2 * PN * PN; idx += NTHREADS) {
        const int m = idx / 484, q = idx - m * 484;
        const int ii = q / PN, jj = q - ii * PN;
        const float dx = sm[OFF_CRD + m*68 + ii*3+0] - sm[OFF_CRD + m*68 + jj*3+0];
        const float dy = sm[OFF_CRD + m*68 + ii*3+1] - sm[OFF_CRD + m*68 + jj*3+1];
        const float dz = sm[OFF_CRD + m*68 + ii*3+2] - sm[OFF_CRD + m*68 + jj*3+2];
        sm[OFF_EA + m*484 + q] = dx*dx + dy*dy + dz*dz;
    }
    /* ordered before use by the weight-staging barrier below */

    ull* const wbu = (ull*)(sm + OFF_WB) + (size_t)w * 512;
    ull* const act = wbu + hw * 256;     /* my half's 4 edges */
    float* const wbf = (float*)wbu;

    for (int l = 0; l < LN; ++l) {
        const float* s1 = ew1 + l * 8320;     /* 130x64, rows 0..127 read from global */
        /* ---- stage this layer's weights ---- */
        {
            const float* s2 = ew2 + l * 4096;
            for (int q = tid; q < 4096; q += NTHREADS) sm[OFF_EW2 + q] = s2[q];
            const float* s5 = cw1 + l * 4096;
            for (int q = tid; q < 4096; q += NTHREADS) sm[OFF_CW1 + q] = s5[q];
            const float* s3 = nw1 + l * 8192;
            for (int q = tid; q < 8192; q += NTHREADS) sm[OFF_NW1 + q] = s3[q];
            const float* s4 = nw2 + l * 4096;
            for (int q = tid; q < 4096; q += NTHREADS) sm[OFF_NW2 + q] = s4[q];
            if (tid < 128) sm[OFF_EW1R + tid] = s1[128 * 64 + tid];
            if (tid >= 128 && tid < 192) {
                const int o = tid - 128;
                sm[OFF_EB1 + o] = eb1[l * 64 + o];
                sm[OFF_EB2 + o] = eb2[l * 64 + o];
                sm[OFF_NB1 + o] = nb1[l * 64 + o];
                sm[OFF_NB2 + o] = nb2[l * 64 + o];
                sm[OFF_CB1 + o] = cb1[l * 64 + o];
                sm[OFF_CW2 + o] = cw2[l * 64 + o];
                sm[OFF_AW + o]  = aw[l * 64 + o];
            }
            if (tid == 0) sm[OFF_AB] = ab[l];
        }
        __syncthreads();

        /* ---- phase 1: Hr/Hc for node i, both molecules (ew1 from global/L2) ---- */
        {
            ull r2a = 0ull, c2a = 0ull, r2b = 0ull, c2b = 0ull;
            const float* hA = &sm[OFF_H + i * 64];
            const float* hB = &sm[OFF_H + 1408 + i * 64];
#pragma unroll 4
            for (int k = 0; k < HN; ++k) {
                const ull wr = *(const ull*)&s1[k * 64 + 2 * lane];
                const ull wc = *(const ull*)&s1[(64 + k) * 64 + 2 * lane];
                const float aA = hA[k]; const ull apA = pack2(aA, aA);
                const float aB = hB[k]; const ull apB = pack2(aB, aB);
                ffma2(r2a, apA, wr); ffma2(c2a, apA, wc);
                ffma2(r2b, apB, wr); ffma2(c2b, apB, wc);
            }
            *(ull*)&sm[OFF_HR + i * 64 + 2 * lane] = r2a;
            *(ull*)&sm[OFF_HC + i * 64 + 2 * lane] = c2a;
            *(ull*)&sm[OFF_HR + 1408 + i * 64 + 2 * lane] = r2b;
            *(ull*)&sm[OFF_HC + 1408 + i * 64 + 2 * lane] = c2b;
        }
        __syncthreads();

        /* ---- phase 2: 21 edges per molecule, 8 per pass (3 passes/mol) ----
           agg/dc kept in registers for BOTH molecules; staged into wbf only
           after the mol loop, when act scratch is dead (R8 fix). */
        float dcAll[2][3];
        float agAll[2][4];
#pragma unroll
        for (int mol = 0; mol < 2; ++mol) {
            const int mo68 = mol * 68, mo14 = mol * 1408, mo484 = mol * 484;
            float ag0 = 0.f, ag1 = 0.f, ag2 = 0.f, ag3 = 0.f;
            float dc0 = 0.f, dc1 = 0.f, dc2 = 0.f;
#pragma unroll 1
            for (int p = 0; p < 3; ++p) {
                /* per-pass constants (cheap broadcast LDS, keeps regs low) */
                const ulonglong2 w128q = *(const ulonglong2*)&sm[OFF_EW1R + c4];
                const ulonglong2 w129q = *(const ulonglong2*)&sm[OFF_EW1R + 64 + c4];
                const ulonglong2 b1q   = *(const ulonglong2*)&sm[OFF_EB1 + c4];
                const ulonglong2 hrq   = *(const ulonglong2*)&sm[OFF_HR + mo14 + i * 64 + c4];
                const float cix = sm[OFF_CRD + mo68 + i * 3 + 0];
                const float ciy = sm[OFF_CRD + mo68 + i * 3 + 1];
                const float ciz = sm[OFF_CRD + mo68 + i * 3 + 2];

                /* setup: t1 = silu(e_in @ ew1 + eb1), duplicated in act */
#pragma unroll
                for (int e = 0; e < 4; ++e) {
                    const int r = p * 8 + hw * 4 + e;
                    int j = (r < i) ? r : r + 1;
                    if (r >= PN - 1) j = i;          /* pad: self-edge dummy */
                    const float dx = cix - sm[OFF_CRD + mo68 + j * 3 + 0];
                    const float dy = ciy - sm[OFF_CRD + mo68 + j * 3 + 1];
                    const float dz = ciz - sm[OFF_CRD + mo68 + j * 3 + 2];
                    const float radial = dx * dx + dy * dy + dz * dz;
                    const float eav = sm[OFF_EA + mo484 + i * PN + j];
                    const ulonglong2 hcq = *(const ulonglong2*)&sm[OFF_HC + mo14 + j * 64 + c4];
                    ull p01 = add2(add2(hrq.x, hcq.x), b1q.x);
                    ull p23 = add2(add2(hrq.y, hcq.y), b1q.y);
                    const ull rad2 = pack2(radial, radial);
                    const ull ea2  = pack2(eav, eav);
                    ffma2(p01, rad2, w128q.x); ffma2(p23, rad2, w128q.y);
                    ffma2(p01, ea2,  w129q.x); ffma2(p23, ea2,  w129q.y);
                    float t0, t1v, t2, t3;
                    unpack2(p01, t0, t1v); unpack2(p23, t2, t3);
                    t0 = siluf(t0); t1v = siluf(t1v); t2 = siluf(t2); t3 = siluf(t3);
                    act[e * HN + c4 + 0] = pack2(t0, t0);
                    act[e * HN + c4 + 1] = pack2(t1v, t1v);
                    act[e * HN + c4 + 2] = pack2(t2, t2);
                    act[e * HN + c4 + 3] = pack2(t3, t3);
                }
                __syncwarp();

                /* GEMV2: m = silu(t1 @ ew2 + eb2), gate, agg */
                const ulonglong2 b2q = *(const ulonglong2*)&sm[OFF_EB2 + c4];
                ull u[4][2];
#pragma unroll
                for (int e = 0; e < 4; ++e) { u[e][0] = b2q.x; u[e][1] = b2q.y; }
                gemv4(&sm[OFF_EW2], act, c4, u);

                const float4 aw4 = *(const float4*)&sm[OFF_AW + c4];
                const float abv = sm[OFF_AB];
                float mv[4][4], part[4];
#pragma unroll
                for (int e = 0; e < 4; ++e) {
                    unpack2(u[e][0], mv[e][0], mv[e][1]);
                    unpack2(u[e][1], mv[e][2], mv[e][3]);
                    mv[e][0] = siluf(mv[e][0]); mv[e][1] = siluf(mv[e][1]);
                    mv[e][2] = siluf(mv[e][2]); mv[e][3] = siluf(mv[e][3]);
                    part[e] = mv[e][0] * aw4.x + mv[e][1] * aw4.y
                            + mv[e][2] * aw4.z + mv[e][3] * aw4.w;
                }
#pragma unroll
                for (int off = 1; off < 16; off <<= 1)
#pragma unroll
                    for (int e = 0; e < 4; ++e)
                        part[e] += __shfl_xor_sync(0xffffffffu, part[e], off);
#pragma unroll
                for (int e = 0; e < 4; ++e) {
                    const float gate = sigmf_(part[e] + abv);
                    mv[e][0] *= gate; mv[e][1] *= gate;
                    mv[e][2] *= gate; mv[e][3] *= gate;
                    if (p * 8 + hw * 4 + e < PN - 1) {   /* valid edge */
                        ag0 += mv[e][0]; ag1 += mv[e][1];
                        ag2 += mv[e][2]; ag3 += mv[e][3];
                    }
                }
                __syncwarp();   /* gemv2 reads of t1 complete */
#pragma unroll
                for (int e = 0; e < 4; ++e) {
                    act[e * HN + c4 + 0] = pack2(mv[e][0], mv[e][0]);
                    act[e * HN + c4 + 1] = pack2(mv[e][1], mv[e][1]);
                    act[e * HN + c4 + 2] = pack2(mv[e][2], mv[e][2]);
                    act[e * HN + c4 + 3] = pack2(mv[e][3], mv[e][3]);
                }
                __syncwarp();

                /* GEMV3: c1 = silu(m @ cw1 + cb1); scal = tanh(c1 @ cw2)*CR */
                const ulonglong2 cbq = *(const ulonglong2*)&sm[OFF_CB1 + c4];
                ull q[4][2];
#pragma unroll
                for (int e = 0; e < 4; ++e) { q[e][0] = cbq.x; q[e][1] = cbq.y; }
                gemv4(&sm[OFF_CW1], act, c4, q);

                const float4 cw4 = *(const float4*)&sm[OFF_CW2 + c4];
                float s[4];
#pragma unroll
                for (int e = 0; e < 4; ++e) {
                    float x0, x1, x2, x3;
                    unpack2(q[e][0], x0, x1); unpack2(q[e][1], x2, x3);
                    s[e] = siluf(x0) * cw4.x + siluf(x1) * cw4.y
                         + siluf(x2) * cw4.z + siluf(x3) * cw4.w;
                }
#pragma unroll
                for (int off = 1; off < 16; off <<= 1)
#pragma unroll
                    for (int e = 0; e < 4; ++e)
                        s[e] += __shfl_xor_sync(0xffffffffu, s[e], off);
                /* recompute norm_diff (saves live registers across the gemvs) */
#pragma unroll
                for (int e = 0; e < 4; ++e) {
                    const int r = p * 8 + hw * 4 + e;
                    int j = (r < i) ? r : r + 1;
                    if (r >= PN - 1) j = i;
                    const float dx = cix - sm[OFF_CRD + mo68 + j * 3 + 0];
                    const float dy = ciy - sm[OFF_CRD + mo68 + j * 3 + 1];
                    const float dz = ciz - sm[OFF_CRD + mo68 + j * 3 + 2];
                    const float radial = dx * dx + dy * dy + dz * dz;
                    const float inv = 1.f / (sqrtf(radial) + 1.f);
                    const float scal = tanhf(s[e]) * CRC * inv;
                    dc0 += dx * scal;
                    dc1 += dy * scal;
                    dc2 += dz * scal;
                }
                __syncwarp();   /* gemv3 reads done before next pass rewrites act */
            }
            /* combine half-warps (disjoint edges) */
            dc0 += __shfl_xor_sync(0xffffffffu, dc0, 16);
            dc1 += __shfl_xor_sync(0xffffffffu, dc1, 16);
            dc2 += __shfl_xor_sync(0xffffffffu, dc2, 16);
            ag0 += __shfl_xor_sync(0xffffffffu, ag0, 16);
            ag1 += __shfl_xor_sync(0xffffffffu, ag1, 16);
            ag2 += __shfl_xor_sync(0xffffffffu, ag2, 16);
            ag3 += __shfl_xor_sync(0xffffffffu, ag3, 16);
            agAll[mol][0] = ag0; agAll[mol][1] = ag1;
            agAll[mol][2] = ag2; agAll[mol][3] = ag3;
            dcAll[mol][0] = dc0; dcAll[mol][1] = dc1; dcAll[mol][2] = dc2;
        }
        /* stage agg for BOTH molecules now that act scratch is dead */
        __syncwarp();
        if (hw == 0) {
#pragma unroll
            for (int m = 0; m < 2; ++m) {
                wbf[m * 64 + c4 + 0] = agAll[m][0];
                wbf[m * 64 + c4 + 1] = agAll[m][1];
                wbf[m * 64 + c4 + 2] = agAll[m][2];
                wbf[m * 64 + c4 + 3] = agAll[m][3];
            }
        }
        __syncthreads();   /* all reads of coord/Hr/Hc complete; agg staged */

        /* ---- phase 3: coord update + node MLP for node i, both molecules ---- */
#pragma unroll
        for (int m = 0; m < 2; ++m) {
            if (lane == 0) {
                sm[OFF_CRD + m * 68 + i * 3 + 0] += dcAll[m][0];
                sm[OFF_CRD + m * 68 + i * 3 + 1] += dcAll[m][1];
                sm[OFF_CRD + m * 68 + i * 3 + 2] += dcAll[m][2];
            }
            ull g2 = *(const ull*)&sm[OFF_NB1 + 2 * lane];
#pragma unroll 8
            for (int k = 0; k < HN; ++k) {
                const float a = sm[OFF_H + m * 1408 + i * 64 + k];
                ffma2(g2, pack2(a, a), *(const ull*)&sm[OFF_NW1 + k * HN + 2 * lane]);
            }
#pragma unroll 8
            for (int k = 0; k < HN; ++k) {
                const float a = wbf[m * 64 + k];
                ffma2(g2, pack2(a, a), *(const ull*)&sm[OFF_NW1 + (HN + k) * HN + 2 * lane]);
            }
            float g0, g1; unpack2(g2, g0, g1);
            g0 = siluf(g0); g1 = siluf(g1);
            wbf[128 + m * 64 + 2 * lane] = g0;
            wbf[128 + m * 64 + 2 * lane + 1] = g1;
            __syncwarp();
            ull o2 = *(const ull*)&sm[OFF_NB2 + 2 * lane];
#pragma unroll 8
            for (int k = 0; k < HN; ++k) {
                const float a = wbf[128 + m * 64 + k];
                ffma2(o2, pack2(a, a), *(const ull*)&sm[OFF_NW2 + k * HN + 2 * lane]);
            }
            float o0, o1; unpack2(o2, o0, o1);
            sm[OFF_H + m * 1408 + i * 64 + 2 * lane]     += o0;
            sm[OFF_H + m * 1408 + i * 64 + 2 * lane + 1] += o1;
            __syncwarp();
        }
        __syncthreads();
    } /* layer loop */

    /* ---- velocity + mean removal (both molecules) ---- */
    for (int idx = tid; idx < 2 * PN * DN; idx += NTHREADS) {
        const int m = idx / 66, rem = idx - m * 66;
        sm[OFF_VEL + m * 68 + rem] = sm[OFF_CRD + m * 68 + rem] - sm[OFF_CR0 + m * 68 + rem];
    }
    __syncthreads();
    if (tid < 6) {
        const int m = tid / 3, d = tid - m * 3;
        float s = 0.f;
        for (int k = 0; k < PN; ++k) s += sm[OFF_VEL + m * 68 + k * 3 + d];
        sm[OFF_MEAN + m * 4 + d] = s * (1.f / PN);
    }
    __syncthreads();
    for (int idx = tid; idx < 2 * PN * DN; idx += NTHREADS) {
        const int m = idx / 66, rem = idx - m * 66;
        out[(b0 + m) * 66 + rem] = sm[OFF_VEL + m * 68 + rem] - sm[OFF_MEAN + m * 4 + rem % 3];
    }
}

extern "C" void kernel_launch(void* const* d_in, const int* in_sizes, int n_in,
                              void* d_out, int out_size)
{
    const float* t    = (const float*)d_in[0];
    const float* x    = (const float*)d_in[1];
    const float* embW = (const float*)d_in[2];
    const float* embb = (const float*)d_in[3];
    /* d_in[4] out_W, d_in[5] out_b: dead code (output depends only on coords) */
    const float* ew1  = (const float*)d_in[6];
    const float* eb1  = (const float*)d_in[7];
    const float* ew2  = (const float*)d_in[8];
    const float* eb2  = (const float*)d_in[9];
    const float* nw1  = (const float*)d_in[10];
    const float* nb1  = (const float*)d_in[11];
    const float* nw2  = (const float*)d_in[12];
    const float* nb2  = (const float*)d_in[13];
    const float* cw1  = (const float*)d_in[14];
    const float* cb1  = (const float*)d_in[15];
    const float* cw2  = (const float*)d_in[16];
    const float* aw   = (const float*)d_in[17];
    const float* ab   = (const float*)d_in[18];
    /* d_in[19] rows, d_in[20] cols: structure known analytically */

    const int B = in_sizes[0];
    const size_t smem = (size_t)SMEM_FLOATS * sizeof(float);
    cudaFuncSetAttribute(egnn_kernel, cudaFuncAttributeMaxDynamicSharedMemorySize, (int)smem);
    egnn_kernel<<<B / 2, NTHREADS, smem>>>(t, x, embW, embb, ew1, eb1, ew2, eb2,
                                           nw1, nb1, nw2, nb2, cw1, cb1, cw2, aw, ab,
                                           (float*)d_out);
}

// round 10
// speedup vs baseline: 2.5369x; 1.2677x over previous
#include <cuda_runtime.h>
#include <math.h>

#define PN 22
#define DN 3
#define HN 64
#define LN 5
#define NWARP 22
#define NTHREADS 704
#define CRC 3.0f       /* 15.0 / 5 layers */
#define LOG2M 7.0f

typedef unsigned long long ull;

/* ---- shared memory layout (floats) ---- */
constexpr int OFF_EW2  = 0;        /* 64*64  */
constexpr int OFF_CW1  = 4096;     /* 64*64  */
constexpr int OFF_NW1  = 8192;     /* 128*64 */
constexpr int OFF_NW2  = 16384;    /* 64*64  */
constexpr int OFF_EW1R = 20480;    /* ew1 rows 128,129 -> 128 floats */
constexpr int OFF_EB1  = 20608;
constexpr int OFF_EB2  = 20672;
constexpr int OFF_NB1  = 20736;
constexpr int OFF_NB2  = 20800;
constexpr int OFF_CB1  = 20864;
constexpr int OFF_CW2  = 20928;
constexpr int OFF_AW   = 20992;
constexpr int OFF_AB   = 21056;    /* +pad */
constexpr int OFF_H    = 21060;    /* 2 * 22*64 */
constexpr int OFF_HR   = 23876;
constexpr int OFF_HC   = 26692;
constexpr int OFF_EA   = 29508;    /* 2 * 484 */
constexpr int OFF_CRD  = 30476;    /* 2 * 68 */
constexpr int OFF_CR0  = 30612;
constexpr int OFF_VEL  = 30748;
constexpr int OFF_MEAN = 30884;    /* 8 */
constexpr int OFF_AGG  = 30892;    /* 22 warps * 2 mols * 64 = 2816 (dedicated; no aliasing) */
constexpr int OFF_WB   = 33708;    /* 22 warps * 16 edges * 64 floats = 22528 */
constexpr int SMEM_FLOATS = 56236; /* 224,944 bytes */

__device__ __forceinline__ float sigmf_(float v) {
    return __fdividef(1.f, 1.f + __expf(-v));
}
__device__ __forceinline__ float siluf(float v) { return v * sigmf_(v); }
__device__ __forceinline__ float tanhfast(float v) {
    /* 1 - 2/(e^{2v}+1); overflow-safe: e^inf -> 1-0=1, e^-inf -> 1-2=-1 */
    const float e2 = __expf(2.f * v);
    return 1.f - __fdividef(2.f, e2 + 1.f);
}

__device__ __forceinline__ void ffma2(ull& d, ull a, ull b) {
    asm("fma.rn.f32x2 %0, %1, %2, %0;" : "+l"(d) : "l"(a), "l"(b));
}
__device__ __forceinline__ ull pack2(float x, float y) {
    ull r; asm("mov.b64 %0, {%1, %2};" : "=l"(r) : "f"(x), "f"(y)); return r;
}
__device__ __forceinline__ void unpack2(ull v, float& x, float& y) {
    asm("mov.b64 {%0, %1}, %2;" : "=f"(x), "=f"(y) : "l"(v));
}

/* 16-edge GEMV (8 per half-warp), 4 cols/lane, float activations.
   Wm: 64x64 row-major. actf: this half's 8 edge rows (64 floats each).
   u[e][0] accumulates cols {c4,c4+1}, u[e][1] cols {c4+2,c4+3}. */
__device__ __forceinline__ void gemv8f(const float* __restrict__ Wm,
                                       const float* __restrict__ actf,
                                       const int c4, ull u[8][2])
{
#pragma unroll 4
    for (int k = 0; k < HN; k += 4) {
        const ulonglong2 w0 = *(const ulonglong2*)&Wm[(k + 0) * HN + c4];
        const ulonglong2 w1 = *(const ulonglong2*)&Wm[(k + 1) * HN + c4];
        const ulonglong2 w2 = *(const ulonglong2*)&Wm[(k + 2) * HN + c4];
        const ulonglong2 w3 = *(const ulonglong2*)&Wm[(k + 3) * HN + c4];
#pragma unroll
        for (int e = 0; e < 8; ++e) {
            const float4 a = *(const float4*)&actf[e * HN + k];
            const ull a0 = pack2(a.x, a.x);
            const ull a1 = pack2(a.y, a.y);
            const ull a2 = pack2(a.z, a.z);
            const ull a3 = pack2(a.w, a.w);
            ffma2(u[e][0], a0, w0.x); ffma2(u[e][1], a0, w0.y);
            ffma2(u[e][0], a1, w1.x); ffma2(u[e][1], a1, w1.y);
            ffma2(u[e][0], a2, w2.x); ffma2(u[e][1], a2, w2.y);
            ffma2(u[e][0], a3, w3.x); ffma2(u[e][1], a3, w3.y);
        }
    }
}

__global__ __launch_bounds__(NTHREADS, 1)
void egnn_kernel(const float* __restrict__ t, const float* __restrict__ x,
                 const float* __restrict__ embW, const float* __restrict__ embb,
                 const float* __restrict__ ew1, const float* __restrict__ eb1,
                 const float* __restrict__ ew2, const float* __restrict__ eb2,
                 const float* __restrict__ nw1, const float* __restrict__ nb1,
                 const float* __restrict__ nw2, const float* __restrict__ nb2,
                 const float* __restrict__ cw1, const float* __restrict__ cb1,
                 const float* __restrict__ cw2, const float* __restrict__ aw,
                 const float* __restrict__ ab, float* __restrict__ out)
{
    extern __shared__ float sm[];
    const int tid = threadIdx.x;
    const int b0 = blockIdx.x * 2;       /* molecules b0, b0+1 */
    const int w = tid >> 5;
    const int lane = tid & 31;
    const int hw = lane >> 4;            /* half-warp: edge subset */
    const int c4 = (lane & 15) * 4;      /* 4 output cols per lane */
    const int i = w;                     /* node owned by this warp (both mols) */

    /* ---- init: coords, h, edge_attr ---- */
    for (int idx = tid; idx < 2 * PN * DN; idx += NTHREADS) {
        const int m = idx / 66, rem = idx - m * 66;
        const float c = x[(b0 + m) * 66 + rem];
        sm[OFF_CRD + m * 68 + rem] = c;
        sm[OFF_CR0 + m * 68 + rem] = c;
    }
    const float tA = t[b0], tB = t[b0 + 1];
    for (int idx = tid; idx < 2 * PN * HN; idx += NTHREADS) {
        const int m = idx / 1408, q = idx - m * 1408;
        const int ii = q >> 6, o = q & 63;
        const float tb = m ? tB : tA;
        sm[OFF_H + m * 1408 + q] = embW[ii * HN + o] + tb * embW[22 * HN + o]
                                 + LOG2M * embW[23 * HN + o] + embb[o];
    }
    __syncthreads();
    for (int idx = tid; idx < 2 * PN * PN; idx += NTHREADS) {
        const int m = idx / 484, q = idx - m * 484;
        const int ii = q / PN, jj = q - ii * PN;
        const float dx = sm[OFF_CRD + m*68 + ii*3+0] - sm[OFF_CRD + m*68 + jj*3+0];
        const float dy = sm[OFF_CRD + m*68 + ii*3+1] - sm[OFF_CRD + m*68 + jj*3+1];
        const float dz = sm[OFF_CRD + m*68 + ii*3+2] - sm[OFF_CRD + m*68 + jj*3+2];
        sm[OFF_EA + m*484 + q] = dx*dx + dy*dy + dz*dz;
    }
    /* ordered before use by the weight-staging barrier below */

    float* const actm = sm + OFF_WB + w * 1024 + hw * 512;   /* my half: 8x64 */
    float* const wbf  = sm + OFF_WB + w * 1024;              /* warp scratch (phase 3) */
    float* const aggp = sm + OFF_AGG + w * 128;              /* [mol][64], dedicated */

    for (int l = 0; l < LN; ++l) {
        const float* s1 = ew1 + l * 8320;    /* rows 0..127 read straight from L2 */
        /* ---- stage this layer's weights ---- */
        {
            const float* s2 = ew2 + l * 4096;
            for (int q = tid; q < 4096; q += NTHREADS) sm[OFF_EW2 + q] = s2[q];
            const float* s5 = cw1 + l * 4096;
            for (int q = tid; q < 4096; q += NTHREADS) sm[OFF_CW1 + q] = s5[q];
            const float* s3 = nw1 + l * 8192;
            for (int q = tid; q < 8192; q += NTHREADS) sm[OFF_NW1 + q] = s3[q];
            const float* s4 = nw2 + l * 4096;
            for (int q = tid; q < 4096; q += NTHREADS) sm[OFF_NW2 + q] = s4[q];
            if (tid < 128) sm[OFF_EW1R + tid] = s1[128 * 64 + tid];
            if (tid >= 128 && tid < 192) {
                const int o = tid - 128;
                sm[OFF_EB1 + o] = eb1[l * 64 + o];
                sm[OFF_EB2 + o] = eb2[l * 64 + o];
                sm[OFF_NB1 + o] = nb1[l * 64 + o];
                sm[OFF_NB2 + o] = nb2[l * 64 + o];
                sm[OFF_CB1 + o] = cb1[l * 64 + o];
                sm[OFF_CW2 + o] = cw2[l * 64 + o];
                sm[OFF_AW + o]  = aw[l * 64 + o];
            }
            if (tid == 0) sm[OFF_AB] = ab[l];
        }
        __syncthreads();

        /* ---- phase 1: Hr/Hc for node i, both molecules (ew1 via L2) ---- */
        {
            ull r2a = 0ull, c2a = 0ull, r2b = 0ull, c2b = 0ull;
            const float* hA = &sm[OFF_H + i * 64];
            const float* hB = &sm[OFF_H + 1408 + i * 64];
#pragma unroll 4
            for (int k = 0; k < HN; ++k) {
                const ull wr = *(const ull*)&s1[k * 64 + 2 * lane];
                const ull wc = *(const ull*)&s1[(64 + k) * 64 + 2 * lane];
                const float aA = hA[k]; const ull apA = pack2(aA, aA);
                const float aB = hB[k]; const ull apB = pack2(aB, aB);
                ffma2(r2a, apA, wr); ffma2(c2a, apA, wc);
                ffma2(r2b, apB, wr); ffma2(c2b, apB, wc);
            }
            *(ull*)&sm[OFF_HR + i * 64 + 2 * lane] = r2a;
            *(ull*)&sm[OFF_HC + i * 64 + 2 * lane] = c2a;
            *(ull*)&sm[OFF_HR + 1408 + i * 64 + 2 * lane] = r2b;
            *(ull*)&sm[OFF_HC + 1408 + i * 64 + 2 * lane] = c2b;
        }
        __syncthreads();

        /* ---- phase 2: unified 48-slot edge stream (2 mols x 21 + 6 pad),
                16 edges per pass (8 per half-warp), 3 passes ---- */
        float dcA0 = 0.f, dcA1 = 0.f, dcA2 = 0.f;
        float dcB0 = 0.f, dcB1 = 0.f, dcB2 = 0.f;
        float agA0 = 0.f, agA1 = 0.f, agA2 = 0.f, agA3 = 0.f;
        float agB0 = 0.f, agB1 = 0.f, agB2 = 0.f, agB3 = 0.f;

#pragma unroll 1
        for (int p = 0; p < 3; ++p) {
            const float4 w128 = *(const float4*)&sm[OFF_EW1R + c4];
            const float4 w129 = *(const float4*)&sm[OFF_EW1R + 64 + c4];
            const float4 b1   = *(const float4*)&sm[OFF_EB1 + c4];

            /* setup: t1 = silu(e_in @ ew1 + eb1) -> actm (plain floats) */
#pragma unroll
            for (int e = 0; e < 8; ++e) {
                const int eg  = p * 16 + hw * 8 + e;
                const int mol = (eg >= 21) ? 1 : 0;
                const int r   = eg - mol * 21;
                const int pad = (r >= PN - 1);
                int j = (r < i) ? r : r + 1;
                if (pad) j = i;
                const int mo68 = mol * 68, mo14 = mol * 1408, mo484 = mol * 484;
                const float dx = sm[OFF_CRD + mo68 + i*3+0] - sm[OFF_CRD + mo68 + j*3+0];
                const float dy = sm[OFF_CRD + mo68 + i*3+1] - sm[OFF_CRD + mo68 + j*3+1];
                const float dz = sm[OFF_CRD + mo68 + i*3+2] - sm[OFF_CRD + mo68 + j*3+2];
                const float radial = dx*dx + dy*dy + dz*dz;
                const float eav = sm[OFF_EA + mo484 + i * PN + j];
                const float4 hr = *(const float4*)&sm[OFF_HR + mo14 + i * 64 + c4];
                const float4 hc = *(const float4*)&sm[OFF_HC + mo14 + j * 64 + c4];
                float4 o;
                o.x = siluf(hr.x + hc.x + b1.x + radial * w128.x + eav * w129.x);
                o.y = siluf(hr.y + hc.y + b1.y + radial * w128.y + eav * w129.y);
                o.z = siluf(hr.z + hc.z + b1.z + radial * w128.z + eav * w129.z);
                o.w = siluf(hr.w + hc.w + b1.w + radial * w128.w + eav * w129.w);
                *(float4*)&actm[e * HN + c4] = o;
            }
            __syncwarp();

            /* GEMV2: m = silu(t1 @ ew2 + eb2) */
            const float4 b2 = *(const float4*)&sm[OFF_EB2 + c4];
            const ull b2lo = pack2(b2.x, b2.y), b2hi = pack2(b2.z, b2.w);
            ull u[8][2];
#pragma unroll
            for (int e = 0; e < 8; ++e) { u[e][0] = b2lo; u[e][1] = b2hi; }
            gemv8f(&sm[OFF_EW2], actm, c4, u);

            const float4 aw4 = *(const float4*)&sm[OFF_AW + c4];
            const float abv  = sm[OFF_AB];
            float mv[8][4], part[8];
#pragma unroll
            for (int e = 0; e < 8; ++e) {
                unpack2(u[e][0], mv[e][0], mv[e][1]);
                unpack2(u[e][1], mv[e][2], mv[e][3]);
                mv[e][0] = siluf(mv[e][0]); mv[e][1] = siluf(mv[e][1]);
                mv[e][2] = siluf(mv[e][2]); mv[e][3] = siluf(mv[e][3]);
                part[e] = mv[e][0]*aw4.x + mv[e][1]*aw4.y + mv[e][2]*aw4.z + mv[e][3]*aw4.w;
            }
#pragma unroll
            for (int off = 1; off < 16; off <<= 1)
#pragma unroll
                for (int e = 0; e < 8; ++e)
                    part[e] += __shfl_xor_sync(0xffffffffu, part[e], off);
#pragma unroll
            for (int e = 0; e < 8; ++e) {
                const int eg  = p * 16 + hw * 8 + e;
                const int mol = (eg >= 21) ? 1 : 0;
                const int pad = (eg - mol * 21 >= PN - 1);
                const float gate = sigmf_(part[e] + abv);
                mv[e][0] *= gate; mv[e][1] *= gate; mv[e][2] *= gate; mv[e][3] *= gate;
                if (!pad) {
                    if (mol == 0) { agA0 += mv[e][0]; agA1 += mv[e][1];
                                    agA2 += mv[e][2]; agA3 += mv[e][3]; }
                    else          { agB0 += mv[e][0]; agB1 += mv[e][1];
                                    agB2 += mv[e][2]; agB3 += mv[e][3]; }
                }
            }
            __syncwarp();   /* gemv2 reads of t1 complete */
#pragma unroll
            for (int e = 0; e < 8; ++e) {
                float4 o; o.x = mv[e][0]; o.y = mv[e][1]; o.z = mv[e][2]; o.w = mv[e][3];
                *(float4*)&actm[e * HN + c4] = o;
            }
            __syncwarp();

            /* GEMV3: c1 = silu(m @ cw1 + cb1); scal = tanh(c1 @ cw2)*CR */
            const float4 cb = *(const float4*)&sm[OFF_CB1 + c4];
            const ull cblo = pack2(cb.x, cb.y), cbhi = pack2(cb.z, cb.w);
            ull q[8][2];
#pragma unroll
            for (int e = 0; e < 8; ++e) { q[e][0] = cblo; q[e][1] = cbhi; }
            gemv8f(&sm[OFF_CW1], actm, c4, q);

            const float4 cw4 = *(const float4*)&sm[OFF_CW2 + c4];
            float s[8];
#pragma unroll
            for (int e = 0; e < 8; ++e) {
                float x0, x1, x2, x3;
                unpack2(q[e][0], x0, x1); unpack2(q[e][1], x2, x3);
                s[e] = siluf(x0)*cw4.x + siluf(x1)*cw4.y + siluf(x2)*cw4.z + siluf(x3)*cw4.w;
            }
#pragma unroll
            for (int off = 1; off < 16; off <<= 1)
#pragma unroll
                for (int e = 0; e < 8; ++e)
                    s[e] += __shfl_xor_sync(0xffffffffu, s[e], off);
#pragma unroll
            for (int e = 0; e < 8; ++e) {
                const int eg  = p * 16 + hw * 8 + e;
                const int mol = (eg >= 21) ? 1 : 0;
                const int r   = eg - mol * 21;
                const int pad = (r >= PN - 1);
                int j = (r < i) ? r : r + 1;
                if (pad) j = i;
                const int mo68 = mol * 68;
                const float dx = sm[OFF_CRD + mo68 + i*3+0] - sm[OFF_CRD + mo68 + j*3+0];
                const float dy = sm[OFF_CRD + mo68 + i*3+1] - sm[OFF_CRD + mo68 + j*3+1];
                const float dz = sm[OFF_CRD + mo68 + i*3+2] - sm[OFF_CRD + mo68 + j*3+2];
                const float radial = dx*dx + dy*dy + dz*dz;
                const float inv = 1.f / (sqrtf(radial) + 1.f);
                const float scal = tanhfast(s[e]) * CRC * inv;
                if (mol == 0) { dcA0 += dx*scal; dcA1 += dy*scal; dcA2 += dz*scal; }
                else          { dcB0 += dx*scal; dcB1 += dy*scal; dcB2 += dz*scal; }
            }
            __syncwarp();   /* gemv3 reads done before next pass rewrites actm */
        }

        /* combine half-warps (disjoint edge sets) */
        dcA0 += __shfl_xor_sync(0xffffffffu, dcA0, 16);
        dcA1 += __shfl_xor_sync(0xffffffffu, dcA1, 16);
        dcA2 += __shfl_xor_sync(0xffffffffu, dcA2, 16);
        dcB0 += __shfl_xor_sync(0xffffffffu, dcB0, 16);
        dcB1 += __shfl_xor_sync(0xffffffffu, dcB1, 16);
        dcB2 += __shfl_xor_sync(0xffffffffu, dcB2, 16);
        agA0 += __shfl_xor_sync(0xffffffffu, agA0, 16);
        agA1 += __shfl_xor_sync(0xffffffffu, agA1, 16);
        agA2 += __shfl_xor_sync(0xffffffffu, agA2, 16);
        agA3 += __shfl_xor_sync(0xffffffffu, agA3, 16);
        agB0 += __shfl_xor_sync(0xffffffffu, agB0, 16);
        agB1 += __shfl_xor_sync(0xffffffffu, agB1, 16);
        agB2 += __shfl_xor_sync(0xffffffffu, agB2, 16);
        agB3 += __shfl_xor_sync(0xffffffffu, agB3, 16);
        if (hw == 0) {
            float4 a0; a0.x = agA0; a0.y = agA1; a0.z = agA2; a0.w = agA3;
            float4 b0v; b0v.x = agB0; b0v.y = agB1; b0v.z = agB2; b0v.w = agB3;
            *(float4*)&aggp[c4] = a0;
            *(float4*)&aggp[64 + c4] = b0v;
        }
        __syncthreads();   /* all phase-2 reads of CRD/HR/HC done; agg staged */

        /* ---- phase 3: coord update + node MLP for node i, both molecules ---- */
#pragma unroll
        for (int m = 0; m < 2; ++m) {
            if (lane == 0) {
                sm[OFF_CRD + m * 68 + i * 3 + 0] += m ? dcB0 : dcA0;
                sm[OFF_CRD + m * 68 + i * 3 + 1] += m ? dcB1 : dcA1;
                sm[OFF_CRD + m * 68 + i * 3 + 2] += m ? dcB2 : dcA2;
            }
            ull g2 = *(const ull*)&sm[OFF_NB1 + 2 * lane];
#pragma unroll 8
            for (int k = 0; k < HN; ++k) {
                const float a = sm[OFF_H + m * 1408 + i * 64 + k];
                ffma2(g2, pack2(a, a), *(const ull*)&sm[OFF_NW1 + k * HN + 2 * lane]);
            }
#pragma unroll 8
            for (int k = 0; k < HN; ++k) {
                const float a = aggp[m * 64 + k];
                ffma2(g2, pack2(a, a), *(const ull*)&sm[OFF_NW1 + (HN + k) * HN + 2 * lane]);
            }
            float g0, g1; unpack2(g2, g0, g1);
            g0 = siluf(g0); g1 = siluf(g1);
            wbf[2 * lane] = g0; wbf[2 * lane + 1] = g1;
            __syncwarp();
            ull o2 = *(const ull*)&sm[OFF_NB2 + 2 * lane];
#pragma unroll 8
            for (int k = 0; k < HN; ++k) {
                const float a = wbf[k];
                ffma2(o2, pack2(a, a), *(const ull*)&sm[OFF_NW2 + k * HN + 2 * lane]);
            }
            float o0, o1; unpack2(o2, o0, o1);
            __syncwarp();   /* wbf reads complete before m=1 overwrites */
            sm[OFF_H + m * 1408 + i * 64 + 2 * lane]     += o0;
            sm[OFF_H + m * 1408 + i * 64 + 2 * lane + 1] += o1;
        }
        __syncthreads();
    } /* layer loop */

    /* ---- velocity + mean removal (both molecules) ---- */
    for (int idx = tid; idx < 2 * PN * DN; idx += NTHREADS) {
        const int m = idx / 66, rem = idx - m * 66;
        sm[OFF_VEL + m * 68 + rem] = sm[OFF_CRD + m * 68 + rem] - sm[OFF_CR0 + m * 68 + rem];
    }
    __syncthreads();
    if (tid < 6) {
        const int m = tid / 3, d = tid - m * 3;
        float s = 0.f;
        for (int k = 0; k < PN; ++k) s += sm[OFF_VEL + m * 68 + k * 3 + d];
        sm[OFF_MEAN + m * 4 + d] = s * (1.f / PN);
    }
    __syncthreads();
    for (int idx = tid; idx < 2 * PN * DN; idx += NTHREADS) {
        const int m = idx / 66, rem = idx - m * 66;
        out[(b0 + m) * 66 + rem] = sm[OFF_VEL + m * 68 + rem] - sm[OFF_MEAN + m * 4 + rem % 3];
    }
}

extern "C" void kernel_launch(void* const* d_in, const int* in_sizes, int n_in,
                              void* d_out, int out_size)
{
    const float* t    = (const float*)d_in[0];
    const float* x    = (const float*)d_in[1];
    const float* embW = (const float*)d_in[2];
    const float* embb = (const float*)d_in[3];
    /* d_in[4] out_W, d_in[5] out_b: dead code (output depends only on coords) */
    const float* ew1  = (const float*)d_in[6];
    const float* eb1  = (const float*)d_in[7];
    const float* ew2  = (const float*)d_in[8];
    const float* eb2  = (const float*)d_in[9];
    const float* nw1  = (const float*)d_in[10];
    const float* nb1  = (const float*)d_in[11];
    const float* nw2  = (const float*)d_in[12];
    const float* nb2  = (const float*)d_in[13];
    const float* cw1  = (const float*)d_in[14];
    const float* cb1  = (const float*)d_in[15];
    const float* cw2  = (const float*)d_in[16];
    const float* aw   = (const float*)d_in[17];
    const float* ab   = (const float*)d_in[18];
    /* d_in[19] rows, d_in[20] cols: structure known analytically */

    const int B = in_sizes[0];
    const size_t smem = (size_t)SMEM_FLOATS * sizeof(float);
    cudaFuncSetAttribute(egnn_kernel, cudaFuncAttributeMaxDynamicSharedMemorySize, (int)smem);
    egnn_kernel<<<B / 2, NTHREADS, smem>>>(t, x, embW, embb, ew1, eb1, ew2, eb2,
                                           nw1, nb1, nw2, nb2, cw1, cb1, cw2, aw, ab,
                                           (float*)d_out);
}

// round 11
// speedup vs baseline: 2.5379x; 1.0004x over previous
#include <cuda_runtime.h>
#include <math.h>

#define PN 22
#define DN 3
#define HN 64
#define LN 5
#define NWARP 22
#define NTHREADS 704
#define CRC 3.0f       /* 15.0 / 5 layers */
#define LOG2M 7.0f

typedef unsigned long long ull;

/* ---- shared memory layout (floats) ---- */
constexpr int OFF_EW2  = 0;        /* 64*64  */
constexpr int OFF_CW1  = 4096;     /* 64*64  */
constexpr int OFF_NW1  = 8192;     /* 128*64 */
constexpr int OFF_NW2  = 16384;    /* 64*64  */
constexpr int OFF_EW1R = 20480;    /* ew1 rows 128,129 -> 128 floats */
constexpr int OFF_EB1  = 20608;
constexpr int OFF_EB2  = 20672;
constexpr int OFF_NB1  = 20736;
constexpr int OFF_NB2  = 20800;
constexpr int OFF_CB1  = 20864;
constexpr int OFF_CW2  = 20928;
constexpr int OFF_AW   = 20992;
constexpr int OFF_AB   = 21056;    /* +pad */
constexpr int OFF_H    = 21060;    /* 2 * 22*64 */
constexpr int OFF_HR   = 23876;
constexpr int OFF_HC   = 26692;
constexpr int OFF_EA   = 29508;    /* 2 * 484 */
constexpr int OFF_CRD  = 30476;    /* 2 * 68 */
constexpr int OFF_CR0  = 30612;
constexpr int OFF_VEL  = 30748;
constexpr int OFF_MEAN = 30884;    /* 8 */
constexpr int OFF_AGG  = 30892;    /* 22 warps * 2 mols * 64 = 2816 (dedicated; no aliasing) */
constexpr int OFF_WB   = 33708;    /* 22 warps * 16 edges * 64 floats = 22528 */
constexpr int SMEM_FLOATS = 56236; /* 224,944 bytes */

__device__ __forceinline__ float sigmf_(float v) {
    return __fdividef(1.f, 1.f + __expf(-v));
}
__device__ __forceinline__ float siluf(float v) { return v * sigmf_(v); }
__device__ __forceinline__ float tanhfast(float v) {
    /* 1 - 2/(e^{2v}+1); overflow-safe: e^inf -> 1-0=1, e^-inf -> 1-2=-1 */
    const float e2 = __expf(2.f * v);
    return 1.f - __fdividef(2.f, e2 + 1.f);
}

__device__ __forceinline__ void ffma2(ull& d, ull a, ull b) {
    asm("fma.rn.f32x2 %0, %1, %2, %0;" : "+l"(d) : "l"(a), "l"(b));
}
__device__ __forceinline__ ull pack2(float x, float y) {
    ull r; asm("mov.b64 %0, {%1, %2};" : "=l"(r) : "f"(x), "f"(y)); return r;
}
__device__ __forceinline__ void unpack2(ull v, float& x, float& y) {
    asm("mov.b64 {%0, %1}, %2;" : "=f"(x), "=f"(y) : "l"(v));
}

/* 16-edge GEMV (8 per half-warp), 4 cols/lane, float activations.
   Wm: 64x64 row-major. actf: this half's 8 edge rows (64 floats each).
   u[e][0] accumulates cols {c4,c4+1}, u[e][1] cols {c4+2,c4+3}. */
__device__ __forceinline__ void gemv8f(const float* __restrict__ Wm,
                                       const float* __restrict__ actf,
                                       const int c4, ull u[8][2])
{
#pragma unroll 4
    for (int k = 0; k < HN; k += 4) {
        const ulonglong2 w0 = *(const ulonglong2*)&Wm[(k + 0) * HN + c4];
        const ulonglong2 w1 = *(const ulonglong2*)&Wm[(k + 1) * HN + c4];
        const ulonglong2 w2 = *(const ulonglong2*)&Wm[(k + 2) * HN + c4];
        const ulonglong2 w3 = *(const ulonglong2*)&Wm[(k + 3) * HN + c4];
#pragma unroll
        for (int e = 0; e < 8; ++e) {
            const float4 a = *(const float4*)&actf[e * HN + k];
            const ull a0 = pack2(a.x, a.x);
            const ull a1 = pack2(a.y, a.y);
            const ull a2 = pack2(a.z, a.z);
            const ull a3 = pack2(a.w, a.w);
            ffma2(u[e][0], a0, w0.x); ffma2(u[e][1], a0, w0.y);
            ffma2(u[e][0], a1, w1.x); ffma2(u[e][1], a1, w1.y);
            ffma2(u[e][0], a2, w2.x); ffma2(u[e][1], a2, w2.y);
            ffma2(u[e][0], a3, w3.x); ffma2(u[e][1], a3, w3.y);
        }
    }
}

__global__ __launch_bounds__(NTHREADS, 1)
void egnn_kernel(const float* __restrict__ t, const float* __restrict__ x,
                 const float* __restrict__ embW, const float* __restrict__ embb,
                 const float* __restrict__ ew1, const float* __restrict__ eb1,
                 const float* __restrict__ ew2, const float* __restrict__ eb2,
                 const float* __restrict__ nw1, const float* __restrict__ nb1,
                 const float* __restrict__ nw2, const float* __restrict__ nb2,
                 const float* __restrict__ cw1, const float* __restrict__ cb1,
                 const float* __restrict__ cw2, const float* __restrict__ aw,
                 const float* __restrict__ ab, float* __restrict__ out)
{
    extern __shared__ float sm[];
    const int tid = threadIdx.x;
    const int b0 = blockIdx.x * 2;       /* molecules b0, b0+1 */
    const int w = tid >> 5;
    const int lane = tid & 31;
    const int hw = lane >> 4;            /* half-warp: edge subset */
    const int c4 = (lane & 15) * 4;      /* 4 output cols per lane */
    const int i = w;                     /* node owned by this warp (both mols) */

    /* ---- init: coords, h, edge_attr ---- */
    for (int idx = tid; idx < 2 * PN * DN; idx += NTHREADS) {
        const int m = idx / 66, rem = idx - m * 66;
        const float c = x[(b0 + m) * 66 + rem];
        sm[OFF_CRD + m * 68 + rem] = c;
        sm[OFF_CR0 + m * 68 + rem] = c;
    }
    const float tA = t[b0], tB = t[b0 + 1];
    for (int idx = tid; idx < 2 * PN * HN; idx += NTHREADS) {
        const int m = idx / 1408, q = idx - m * 1408;
        const int ii = q >> 6, o = q & 63;
        const float tb = m ? tB : tA;
        sm[OFF_H + m * 1408 + q] = embW[ii * HN + o] + tb * embW[22 * HN + o]
                                 + LOG2M * embW[23 * HN + o] + embb[o];
    }
    __syncthreads();
    for (int idx = tid; idx < 2 * PN * PN; idx += NTHREADS) {
        const int m = idx / 484, q = idx - m * 484;
        const int ii = q / PN, jj = q - ii * PN;
        const float dx = sm[OFF_CRD + m*68 + ii*3+0] - sm[OFF_CRD + m*68 + jj*3+0];
        const float dy = sm[OFF_CRD + m*68 + ii*3+1] - sm[OFF_CRD + m*68 + jj*3+1];
        const float dz = sm[OFF_CRD + m*68 + ii*3+2] - sm[OFF_CRD + m*68 + jj*3+2];
        sm[OFF_EA + m*484 + q] = dx*dx + dy*dy + dz*dz;
    }
    /* ordered before use by the weight-staging barrier below */

    float* const actm = sm + OFF_WB + w * 1024 + hw * 512;   /* my half: 8x64 */
    float* const wbf  = sm + OFF_WB + w * 1024;              /* warp scratch (phase 3) */
    float* const aggp = sm + OFF_AGG + w * 128;              /* [mol][64], dedicated */

    for (int l = 0; l < LN; ++l) {
        const float* s1 = ew1 + l * 8320;    /* rows 0..127 read straight from L2 */
        /* ---- stage this layer's weights ---- */
        {
            const float* s2 = ew2 + l * 4096;
            for (int q = tid; q < 4096; q += NTHREADS) sm[OFF_EW2 + q] = s2[q];
            const float* s5 = cw1 + l * 4096;
            for (int q = tid; q < 4096; q += NTHREADS) sm[OFF_CW1 + q] = s5[q];
            const float* s3 = nw1 + l * 8192;
            for (int q = tid; q < 8192; q += NTHREADS) sm[OFF_NW1 + q] = s3[q];
            const float* s4 = nw2 + l * 4096;
            for (int q = tid; q < 4096; q += NTHREADS) sm[OFF_NW2 + q] = s4[q];
            if (tid < 128) sm[OFF_EW1R + tid] = s1[128 * 64 + tid];
            if (tid >= 128 && tid < 192) {
                const int o = tid - 128;
                sm[OFF_EB1 + o] = eb1[l * 64 + o];
                sm[OFF_EB2 + o] = eb2[l * 64 + o];
                sm[OFF_NB1 + o] = nb1[l * 64 + o];
                sm[OFF_NB2 + o] = nb2[l * 64 + o];
                sm[OFF_CB1 + o] = cb1[l * 64 + o];
                sm[OFF_CW2 + o] = cw2[l * 64 + o];
                sm[OFF_AW + o]  = aw[l * 64 + o];
            }
            if (tid == 0) sm[OFF_AB] = ab[l];
        }
        __syncthreads();

        /* ---- phase 1: Hr/Hc for node i, both molecules (ew1 via L2) ---- */
        {
            ull r2a = 0ull, c2a = 0ull, r2b = 0ull, c2b = 0ull;
            const float* hA = &sm[OFF_H + i * 64];
            const float* hB = &sm[OFF_H + 1408 + i * 64];
#pragma unroll 4
            for (int k = 0; k < HN; ++k) {
                const ull wr = *(const ull*)&s1[k * 64 + 2 * lane];
                const ull wc = *(const ull*)&s1[(64 + k) * 64 + 2 * lane];
                const float aA = hA[k]; const ull apA = pack2(aA, aA);
                const float aB = hB[k]; const ull apB = pack2(aB, aB);
                ffma2(r2a, apA, wr); ffma2(c2a, apA, wc);
                ffma2(r2b, apB, wr); ffma2(c2b, apB, wc);
            }
            *(ull*)&sm[OFF_HR + i * 64 + 2 * lane] = r2a;
            *(ull*)&sm[OFF_HC + i * 64 + 2 * lane] = c2a;
            *(ull*)&sm[OFF_HR + 1408 + i * 64 + 2 * lane] = r2b;
            *(ull*)&sm[OFF_HC + 1408 + i * 64 + 2 * lane] = c2b;
        }
        __syncthreads();

        /* ---- phase 2: unified 48-slot edge stream (2 mols x 21 + 6 pad),
                16 edges per pass (8 per half-warp), 3 passes ---- */
        float dcA0 = 0.f, dcA1 = 0.f, dcA2 = 0.f;
        float dcB0 = 0.f, dcB1 = 0.f, dcB2 = 0.f;
        float agA0 = 0.f, agA1 = 0.f, agA2 = 0.f, agA3 = 0.f;
        float agB0 = 0.f, agB1 = 0.f, agB2 = 0.f, agB3 = 0.f;

#pragma unroll 1
        for (int p = 0; p < 3; ++p) {
            const float4 w128 = *(const float4*)&sm[OFF_EW1R + c4];
            const float4 w129 = *(const float4*)&sm[OFF_EW1R + 64 + c4];
            const float4 b1   = *(const float4*)&sm[OFF_EB1 + c4];

            /* setup: t1 = silu(e_in @ ew1 + eb1) -> actm (plain floats) */
#pragma unroll
            for (int e = 0; e < 8; ++e) {
                const int eg  = p * 16 + hw * 8 + e;
                const int mol = (eg >= 21) ? 1 : 0;
                const int r   = eg - mol * 21;
                const int pad = (r >= PN - 1);
                int j = (r < i) ? r : r + 1;
                if (pad) j = i;
                const int mo68 = mol * 68, mo14 = mol * 1408, mo484 = mol * 484;
                const float dx = sm[OFF_CRD + mo68 + i*3+0] - sm[OFF_CRD + mo68 + j*3+0];
                const float dy = sm[OFF_CRD + mo68 + i*3+1] - sm[OFF_CRD + mo68 + j*3+1];
                const float dz = sm[OFF_CRD + mo68 + i*3+2] - sm[OFF_CRD + mo68 + j*3+2];
                const float radial = dx*dx + dy*dy + dz*dz;
                const float eav = sm[OFF_EA + mo484 + i * PN + j];
                const float4 hr = *(const float4*)&sm[OFF_HR + mo14 + i * 64 + c4];
                const float4 hc = *(const float4*)&sm[OFF_HC + mo14 + j * 64 + c4];
                float4 o;
                o.x = siluf(hr.x + hc.x + b1.x + radial * w128.x + eav * w129.x);
                o.y = siluf(hr.y + hc.y + b1.y + radial * w128.y + eav * w129.y);
                o.z = siluf(hr.z + hc.z + b1.z + radial * w128.z + eav * w129.z);
                o.w = siluf(hr.w + hc.w + b1.w + radial * w128.w + eav * w129.w);
                *(float4*)&actm[e * HN + c4] = o;
            }
            __syncwarp();

            /* GEMV2: m = silu(t1 @ ew2 + eb2) */
            const float4 b2 = *(const float4*)&sm[OFF_EB2 + c4];
            const ull b2lo = pack2(b2.x, b2.y), b2hi = pack2(b2.z, b2.w);
            ull u[8][2];
#pragma unroll
            for (int e = 0; e < 8; ++e) { u[e][0] = b2lo; u[e][1] = b2hi; }
            gemv8f(&sm[OFF_EW2], actm, c4, u);

            const float4 aw4 = *(const float4*)&sm[OFF_AW + c4];
            const float abv  = sm[OFF_AB];
            float mv[8][4], part[8];
#pragma unroll
            for (int e = 0; e < 8; ++e) {
                unpack2(u[e][0], mv[e][0], mv[e][1]);
                unpack2(u[e][1], mv[e][2], mv[e][3]);
                mv[e][0] = siluf(mv[e][0]); mv[e][1] = siluf(mv[e][1]);
                mv[e][2] = siluf(mv[e][2]); mv[e][3] = siluf(mv[e][3]);
                part[e] = mv[e][0]*aw4.x + mv[e][1]*aw4.y + mv[e][2]*aw4.z + mv[e][3]*aw4.w;
            }
#pragma unroll
            for (int off = 1; off < 16; off <<= 1)
#pragma unroll
                for (int e = 0; e < 8; ++e)
                    part[e] += __shfl_xor_sync(0xffffffffu, part[e], off);
#pragma unroll
            for (int e = 0; e < 8; ++e) {
                const int eg  = p * 16 + hw * 8 + e;
                const int mol = (eg >= 21) ? 1 : 0;
                const int pad = (eg - mol * 21 >= PN - 1);
                const float gate = sigmf_(part[e] + abv);
                mv[e][0] *= gate; mv[e][1] *= gate; mv[e][2] *= gate; mv[e][3] *= gate;
                if (!pad) {
                    if (mol == 0) { agA0 += mv[e][0]; agA1 += mv[e][1];
                                    agA2 += mv[e][2]; agA3 += mv[e][3]; }
                    else          { agB0 += mv[e][0]; agB1 += mv[e][1];
                                    agB2 += mv[e][2]; agB3 += mv[e][3]; }
                }
            }
            __syncwarp();   /* gemv2 reads of t1 complete */
#pragma unroll
            for (int e = 0; e < 8; ++e) {
                float4 o; o.x = mv[e][0]; o.y = mv[e][1]; o.z = mv[e][2]; o.w = mv[e][3];
                *(float4*)&actm[e * HN + c4] = o;
            }
            __syncwarp();

            /* GEMV3: c1 = silu(m @ cw1 + cb1); scal = tanh(c1 @ cw2)*CR */
            const float4 cb = *(const float4*)&sm[OFF_CB1 + c4];
            const ull cblo = pack2(cb.x, cb.y), cbhi = pack2(cb.z, cb.w);
            ull q[8][2];
#pragma unroll
            for (int e = 0; e < 8; ++e) { q[e][0] = cblo; q[e][1] = cbhi; }
            gemv8f(&sm[OFF_CW1], actm, c4, q);

            const float4 cw4 = *(const float4*)&sm[OFF_CW2 + c4];
            float s[8];
#pragma unroll
            for (int e = 0; e < 8; ++e) {
                float x0, x1, x2, x3;
                unpack2(q[e][0], x0, x1); unpack2(q[e][1], x2, x3);
                s[e] = siluf(x0)*cw4.x + siluf(x1)*cw4.y + siluf(x2)*cw4.z + siluf(x3)*cw4.w;
            }
#pragma unroll
            for (int off = 1; off < 16; off <<= 1)
#pragma unroll
                for (int e = 0; e < 8; ++e)
                    s[e] += __shfl_xor_sync(0xffffffffu, s[e], off);
#pragma unroll
            for (int e = 0; e < 8; ++e) {
                const int eg  = p * 16 + hw * 8 + e;
                const int mol = (eg >= 21) ? 1 : 0;
                const int r   = eg - mol * 21;
                const int pad = (r >= PN - 1);
                int j = (r < i) ? r : r + 1;
                if (pad) j = i;
                const int mo68 = mol * 68;
                const float dx = sm[OFF_CRD + mo68 + i*3+0] - sm[OFF_CRD + mo68 + j*3+0];
                const float dy = sm[OFF_CRD + mo68 + i*3+1] - sm[OFF_CRD + mo68 + j*3+1];
                const float dz = sm[OFF_CRD + mo68 + i*3+2] - sm[OFF_CRD + mo68 + j*3+2];
                const float radial = dx*dx + dy*dy + dz*dz;
                const float inv = 1.f / (sqrtf(radial) + 1.f);
                const float scal = tanhfast(s[e]) * CRC * inv;
                if (mol == 0) { dcA0 += dx*scal; dcA1 += dy*scal; dcA2 += dz*scal; }
                else          { dcB0 += dx*scal; dcB1 += dy*scal; dcB2 += dz*scal; }
            }
            __syncwarp();   /* gemv3 reads done before next pass rewrites actm */
        }

        /* combine half-warps (disjoint edge sets) */
        dcA0 += __shfl_xor_sync(0xffffffffu, dcA0, 16);
        dcA1 += __shfl_xor_sync(0xffffffffu, dcA1, 16);
        dcA2 += __shfl_xor_sync(0xffffffffu, dcA2, 16);
        dcB0 += __shfl_xor_sync(0xffffffffu, dcB0, 16);
        dcB1 += __shfl_xor_sync(0xffffffffu, dcB1, 16);
        dcB2 += __shfl_xor_sync(0xffffffffu, dcB2, 16);
        agA0 += __shfl_xor_sync(0xffffffffu, agA0, 16);
        agA1 += __shfl_xor_sync(0xffffffffu, agA1, 16);
        agA2 += __shfl_xor_sync(0xffffffffu, agA2, 16);
        agA3 += __shfl_xor_sync(0xffffffffu, agA3, 16);
        agB0 += __shfl_xor_sync(0xffffffffu, agB0, 16);
        agB1 += __shfl_xor_sync(0xffffffffu, agB1, 16);
        agB2 += __shfl_xor_sync(0xffffffffu, agB2, 16);
        agB3 += __shfl_xor_sync(0xffffffffu, agB3, 16);
        if (hw == 0) {
            float4 a0; a0.x = agA0; a0.y = agA1; a0.z = agA2; a0.w = agA3;
            float4 b0v; b0v.x = agB0; b0v.y = agB1; b0v.z = agB2; b0v.w = agB3;
            *(float4*)&aggp[c4] = a0;
            *(float4*)&aggp[64 + c4] = b0v;
        }
        __syncthreads();   /* all phase-2 reads of CRD/HR/HC done; agg staged */

        /* ---- phase 3: coord update + node MLP for node i, both molecules ---- */
#pragma unroll
        for (int m = 0; m < 2; ++m) {
            if (lane == 0) {
                sm[OFF_CRD + m * 68 + i * 3 + 0] += m ? dcB0 : dcA0;
                sm[OFF_CRD + m * 68 + i * 3 + 1] += m ? dcB1 : dcA1;
                sm[OFF_CRD + m * 68 + i * 3 + 2] += m ? dcB2 : dcA2;
            }
            ull g2 = *(const ull*)&sm[OFF_NB1 + 2 * lane];
#pragma unroll 8
            for (int k = 0; k < HN; ++k) {
                const float a = sm[OFF_H + m * 1408 + i * 64 + k];
                ffma2(g2, pack2(a, a), *(const ull*)&sm[OFF_NW1 + k * HN + 2 * lane]);
            }
#pragma unroll 8
            for (int k = 0; k < HN; ++k) {
                const float a = aggp[m * 64 + k];
                ffma2(g2, pack2(a, a), *(const ull*)&sm[OFF_NW1 + (HN + k) * HN + 2 * lane]);
            }
            float g0, g1; unpack2(g2, g0, g1);
            g0 = siluf(g0); g1 = siluf(g1);
            wbf[2 * lane] = g0; wbf[2 * lane + 1] = g1;
            __syncwarp();
            ull o2 = *(const ull*)&sm[OFF_NB2 + 2 * lane];
#pragma unroll 8
            for (int k = 0; k < HN; ++k) {
                const float a = wbf[k];
                ffma2(o2, pack2(a, a), *(const ull*)&sm[OFF_NW2 + k * HN + 2 * lane]);
            }
            float o0, o1; unpack2(o2, o0, o1);
            __syncwarp();   /* wbf reads complete before m=1 overwrites */
            sm[OFF_H + m * 1408 + i * 64 + 2 * lane]     += o0;
            sm[OFF_H + m * 1408 + i * 64 + 2 * lane + 1] += o1;
        }
        __syncthreads();
    } /* layer loop */

    /* ---- velocity + mean removal (both molecules) ---- */
    for (int idx = tid; idx < 2 * PN * DN; idx += NTHREADS) {
        const int m = idx / 66, rem = idx - m * 66;
        sm[OFF_VEL + m * 68 + rem] = sm[OFF_CRD + m * 68 + rem] - sm[OFF_CR0 + m * 68 + rem];
    }
    __syncthreads();
    if (tid < 6) {
        const int m = tid / 3, d = tid - m * 3;
        float s = 0.f;
        for (int k = 0; k < PN; ++k) s += sm[OFF_VEL + m * 68 + k * 3 + d];
        sm[OFF_MEAN + m * 4 + d] = s * (1.f / PN);
    }
    __syncthreads();
    for (int idx = tid; idx < 2 * PN * DN; idx += NTHREADS) {
        const int m = idx / 66, rem = idx - m * 66;
        out[(b0 + m) * 66 + rem] = sm[OFF_VEL + m * 68 + rem] - sm[OFF_MEAN + m * 4 + rem % 3];
    }
}

extern "C" void kernel_launch(void* const* d_in, const int* in_sizes, int n_in,
                              void* d_out, int out_size)
{
    const float* t    = (const float*)d_in[0];
    const float* x    = (const float*)d_in[1];
    const float* embW = (const float*)d_in[2];
    const float* embb = (const float*)d_in[3];
    /* d_in[4] out_W, d_in[5] out_b: dead code (output depends only on coords) */
    const float* ew1  = (const float*)d_in[6];
    const float* eb1  = (const float*)d_in[7];
    const float* ew2  = (const float*)d_in[8];
    const float* eb2  = (const float*)d_in[9];
    const float* nw1  = (const float*)d_in[10];
    const float* nb1  = (const float*)d_in[11];
    const float* nw2  = (const float*)d_in[12];
    const float* nb2  = (const float*)d_in[13];
    const float* cw1  = (const float*)d_in[14];
    const float* cb1  = (const float*)d_in[15];
    const float* cw2  = (const float*)d_in[16];
    const float* aw   = (const float*)d_in[17];
    const float* ab   = (const float*)d_in[18];
    /* d_in[19] rows, d_in[20] cols: structure known analytically */

    const int B = in_sizes[0];
    const size_t smem = (size_t)SMEM_FLOATS * sizeof(float);
    cudaFuncSetAttribute(egnn_kernel, cudaFuncAttributeMaxDynamicSharedMemorySize, (int)smem);
    egnn_kernel<<<B / 2, NTHREADS, smem>>>(t, x, embW, embb, ew1, eb1, ew2, eb2,
                                           nw1, nb1, nw2, nb2, cw1, cb1, cw2, aw, ab,
                                           (float*)d_out);
}